// round 2
// baseline (speedup 1.0000x reference)
#include <cuda_runtime.h>
#include <math.h>
#include <stdint.h>

// ---------------------------------------------------------------------------
// Problem constants: B=1, D=6, H=128, W=128, C=180, NH=6, HD=30
// WS=(2,8,8) -> N=128 tokens/window, 768 windows, SS=(1,4,4), HID=360
// ---------------------------------------------------------------------------
#define NTOK   98304          // total tokens = 6*128*128
#define CD     180            // C
#define C3     540            // 3*C
#define C2     360            // 2*C (= HID)
#define NWIN   768
#define NHEAD  6
#define HDIM   30
#define NMASK  16384          // 128*128
#define SCALE_F 0.18257418583505536f   // 30^-0.5

// ------------------------- scratch (static, no alloc) ----------------------
__device__ float g_xw   [(size_t)NTOK * CD];   // windowed LN1 out; reused as LN2 out
__device__ float g_qkv_s[(size_t)NTOK * C3];
__device__ float g_qkv_m[(size_t)NTOK * C3];
__device__ float g_xo   [(size_t)NTOK * C2];   // attn concat; reused as MLP hidden
__device__ float g_x1   [(size_t)NTOK * CD];   // x + attn branch
__device__ float g_bias6[NHEAD * NMASK];

// windowed row r -> global token index (encodes roll(-S) + win_part; its own
// inverse path win_rev + roll(+S) lands on the same global index)
__device__ __forceinline__ int win2glob(int r) {
    int w = r >> 7, n = r & 127;
    int dblk = w >> 8, hblk = (w >> 4) & 15, wblk = w & 15;
    int wd = n >> 6,  wh = (n >> 3) & 7,   ww = n & 7;
    int d = dblk * 2 + wd + 1; if (d >= 6) d -= 6;
    int hh = (hblk * 8 + wh + 4) & 127;
    int w2 = (wblk * 8 + ww + 4) & 127;
    return (d * 128 + hh) * 128 + w2;
}

// ------------------------- rel-pos bias gather -----------------------------
__global__ void bias6_kernel(const float* __restrict__ rpb,
                             const int* __restrict__ rpi) {
    int t = blockIdx.x * 256 + threadIdx.x;
    if (t < NHEAD * NMASK) {
        int h = t >> 14, nm = t & (NMASK - 1);
        g_bias6[t] = rpb[rpi[nm] * NHEAD + h];
    }
}

// ------------------------- LayerNorm (warp / token) ------------------------
// mapped=1: gather from win2glob(r) (LN1 + roll + window partition)
// mapped=0: identity rows (LN2)
__global__ void ln_kernel(const float* __restrict__ x,
                          const float* __restrict__ g,
                          const float* __restrict__ b,
                          float* __restrict__ y, int mapped) {
    int r = blockIdx.x * 8 + (threadIdx.x >> 5);
    int lane = threadIdx.x & 31;
    int src = mapped ? win2glob(r) : r;
    const float* xr = x + (size_t)src * CD;
    float vals[6], s = 0.f, s2 = 0.f;
#pragma unroll
    for (int i = 0; i < 6; i++) {
        int c = lane + i * 32;
        float v = (c < CD) ? xr[c] : 0.f;
        vals[i] = v; s += v; s2 += v * v;
    }
#pragma unroll
    for (int o = 16; o; o >>= 1) {
        s  += __shfl_xor_sync(0xffffffffu, s,  o);
        s2 += __shfl_xor_sync(0xffffffffu, s2, o);
    }
    float m = s * (1.f / CD);
    float var = s2 * (1.f / CD) - m * m;
    float rstd = rsqrtf(var + 1e-5f);
    float* yr = y + (size_t)r * CD;
#pragma unroll
    for (int i = 0; i < 6; i++) {
        int c = lane + i * 32;
        if (c < CD) yr[c] = (vals[i] - m) * rstd * g[c] + b[c];
    }
}

// ------------------------- generic tiled fp32 GEMM -------------------------
// C = A(MxK) * B(KxN) + bias, 64x64x32 tiles, 256 thr, 4x4 micro-tile.
// EPI 0: plain store (stride N); optional pb adds pos_bias[row&63][k] to A.
// EPI 1: scatter store to win2glob(r), + resid (stride 180)
// EPI 3: natural store + resid (stride 180)
template<int EPI>
__global__ void gemm64(const float* __restrict__ A, const float* __restrict__ B,
                       const float* __restrict__ bias, float* __restrict__ Cout,
                       int M, int N, int K,
                       const float* __restrict__ pb,
                       const float* __restrict__ resid) {
    __shared__ float As[64][33];
    __shared__ float Bs[32][64];
    int tx = threadIdx.x & 15, ty = threadIdx.x >> 4;
    int row0 = blockIdx.y * 64, col0 = blockIdx.x * 64;
    float acc[4][4] = {};

    for (int k0 = 0; k0 < K; k0 += 32) {
#pragma unroll
        for (int i = 0; i < 8; i++) {
            int lin = threadIdx.x + i * 256;
            int m = lin >> 5, k = lin & 31;
            int gk = k0 + k, gr = row0 + m;
            float v = 0.f;
            if (gk < K) {
                v = A[(size_t)gr * K + gk];
                if (EPI == 0 && pb) v += pb[(gr & 63) * K + gk];
            }
            As[m][k] = v;
        }
#pragma unroll
        for (int i = 0; i < 8; i++) {
            int lin = threadIdx.x + i * 256;
            int k = lin >> 6, c = lin & 63;
            int gk = k0 + k, gc = col0 + c;
            Bs[k][c] = (gk < K && gc < N) ? B[(size_t)gk * N + gc] : 0.f;
        }
        __syncthreads();
#pragma unroll
        for (int kk = 0; kk < 32; kk++) {
            float a[4];
#pragma unroll
            for (int i = 0; i < 4; i++) a[i] = As[ty * 4 + i][kk];
            float4 b4 = *(const float4*)&Bs[kk][tx * 4];
            float bb[4] = {b4.x, b4.y, b4.z, b4.w};
#pragma unroll
            for (int i = 0; i < 4; i++)
#pragma unroll
                for (int j = 0; j < 4; j++) acc[i][j] += a[i] * bb[j];
        }
        __syncthreads();
    }

#pragma unroll
    for (int i = 0; i < 4; i++) {
        int r = row0 + ty * 4 + i;
#pragma unroll
        for (int j = 0; j < 4; j++) {
            int c = col0 + tx * 4 + j;
            if (c < N) {
                float val = acc[i][j] + bias[c];
                if (EPI == 0) {
                    Cout[(size_t)r * N + c] = val;
                } else if (EPI == 1) {
                    int gidx = win2glob(r);
                    Cout[(size_t)gidx * CD + c] = resid[(size_t)gidx * CD + c] + val;
                } else { // EPI == 3
                    Cout[(size_t)r * CD + c] = resid[(size_t)r * CD + c] + val;
                }
            }
        }
    }
}

// ------------------------- fused FC11/FC12 + GEGLU -------------------------
// out = gelu_exact(A*B1 + b1) * (A*B2 + b2);  M x 360, K = 180
__global__ void fc1_kernel(const float* __restrict__ A,
                           const float* __restrict__ B1, const float* __restrict__ b1,
                           const float* __restrict__ B2, const float* __restrict__ b2,
                           float* __restrict__ Cout, int M, int N, int K) {
    __shared__ float As[64][33];
    __shared__ float Bs1[32][64];
    __shared__ float Bs2[32][64];
    int tx = threadIdx.x & 15, ty = threadIdx.x >> 4;
    int row0 = blockIdx.y * 64, col0 = blockIdx.x * 64;
    float acc1[4][4] = {}, acc2[4][4] = {};

    for (int k0 = 0; k0 < K; k0 += 32) {
#pragma unroll
        for (int i = 0; i < 8; i++) {
            int lin = threadIdx.x + i * 256;
            int m = lin >> 5, k = lin & 31;
            int gk = k0 + k, gr = row0 + m;
            As[m][k] = (gk < K) ? A[(size_t)gr * K + gk] : 0.f;
        }
#pragma unroll
        for (int i = 0; i < 8; i++) {
            int lin = threadIdx.x + i * 256;
            int k = lin >> 6, c = lin & 63;
            int gk = k0 + k, gc = col0 + c;
            bool ok = (gk < K && gc < N);
            Bs1[k][c] = ok ? B1[(size_t)gk * N + gc] : 0.f;
            Bs2[k][c] = ok ? B2[(size_t)gk * N + gc] : 0.f;
        }
        __syncthreads();
#pragma unroll
        for (int kk = 0; kk < 32; kk++) {
            float a[4];
#pragma unroll
            for (int i = 0; i < 4; i++) a[i] = As[ty * 4 + i][kk];
            float4 c4 = *(const float4*)&Bs1[kk][tx * 4];
            float4 d4 = *(const float4*)&Bs2[kk][tx * 4];
            float bb1[4] = {c4.x, c4.y, c4.z, c4.w};
            float bb2[4] = {d4.x, d4.y, d4.z, d4.w};
#pragma unroll
            for (int i = 0; i < 4; i++)
#pragma unroll
                for (int j = 0; j < 4; j++) {
                    acc1[i][j] += a[i] * bb1[j];
                    acc2[i][j] += a[i] * bb2[j];
                }
        }
        __syncthreads();
    }

#pragma unroll
    for (int i = 0; i < 4; i++) {
        int r = row0 + ty * 4 + i;
#pragma unroll
        for (int j = 0; j < 4; j++) {
            int c = col0 + tx * 4 + j;
            if (c < N) {
                float u = acc1[i][j] + b1[c];
                float v = acc2[i][j] + b2[c];
                float ge = 0.5f * u * (1.f + erff(u * 0.7071067811865475f));
                Cout[(size_t)r * N + c] = ge * v;
            }
        }
    }
}

// ------------------------- windowed self attention -------------------------
// one block = (window, head); 128 threads = 128 query rows
// dyn smem: ks[128*32] vs[128*32] sc[128*129]  (96.5 KB)
__global__ void attn_self_kernel(const float* __restrict__ qkv,
                                 const float* __restrict__ mask,
                                 float* __restrict__ xo) {
    extern __shared__ float sm[];
    float* ks = sm;                 // 4096
    float* vs = sm + 4096;          // 4096
    float* sc = sm + 8192;          // 128*129
    int w = blockIdx.x / NHEAD, h = blockIdx.x % NHEAD;
    int t = threadIdx.x;
    const float* base = qkv + (size_t)w * 128 * C3;

    for (int idx = t; idx < 128 * HDIM; idx += 128) {
        int m = idx / HDIM, d = idx - m * HDIM;
        ks[m * 32 + d] = base[(size_t)m * C3 + CD  + h * HDIM + d];
        vs[m * 32 + d] = base[(size_t)m * C3 + 2*CD + h * HDIM + d];
    }
    // pre-stage bias+mask into score tile (coalesced global reads)
    const float* bi = g_bias6 + h * NMASK;
    const float* mk = mask + (size_t)w * NMASK;
    for (int idx = t; idx < NMASK; idx += 128) {
        int n = idx >> 7, m = idx & 127;
        sc[n * 129 + m] = bi[idx] + mk[idx];
    }
    __syncthreads();

    float q[HDIM];
#pragma unroll
    for (int d = 0; d < HDIM; d++) q[d] = base[(size_t)t * C3 + h * HDIM + d] * SCALE_F;

    float* srow = sc + t * 129;
    float mx = -1e30f;
    for (int m = 0; m < 128; m++) {
        const float* kr = ks + m * 32;
        float s = srow[m];
#pragma unroll
        for (int d4 = 0; d4 < 7; d4++) {
            float4 k4 = *(const float4*)(kr + d4 * 4);
            s += q[d4*4+0]*k4.x + q[d4*4+1]*k4.y + q[d4*4+2]*k4.z + q[d4*4+3]*k4.w;
        }
        s += q[28] * kr[28] + q[29] * kr[29];
        srow[m] = s;
        mx = fmaxf(mx, s);
    }
    float ssum = 0.f;
    for (int m = 0; m < 128; m++) {
        float p = __expf(srow[m] - mx);
        srow[m] = p; ssum += p;
    }
    float o[HDIM] = {};
    for (int m = 0; m < 128; m++) {
        float p = srow[m];
        const float* vr = vs + m * 32;
#pragma unroll
        for (int d4 = 0; d4 < 7; d4++) {
            float4 v4 = *(const float4*)(vr + d4 * 4);
            o[d4*4+0] += p*v4.x; o[d4*4+1] += p*v4.y;
            o[d4*4+2] += p*v4.z; o[d4*4+3] += p*v4.w;
        }
        o[28] += p * vr[28]; o[29] += p * vr[29];
    }
    float inv = 1.f / ssum;
    float* out = xo + ((size_t)(w * 128 + t)) * C2 + CD + h * HDIM;
#pragma unroll
    for (int d = 0; d < HDIM; d++) out[d] = o[d] * inv;
}

// ------------------------- mutual (cross-frame) attention ------------------
// block = (window, head, part). part 0: x1 = attn(q[64:128], kv[0:64]) -> rows 0..63
//                               part 1: x2 = attn(q[0:64],  kv[64:128]) -> rows 64..127
__global__ void attn_mut_kernel(const float* __restrict__ qkvm,
                                const float* __restrict__ mask,
                                float* __restrict__ xo) {
    __shared__ float ks[64 * 32];
    __shared__ float vs[64 * 32];
    __shared__ float sc[64 * 65];
    int b = blockIdx.x;
    int part = b & 1, h = (b >> 1) % NHEAD, w = b / (2 * NHEAD);
    int t = threadIdx.x;  // 0..63
    const float* base = qkvm + (size_t)w * 128 * C3;
    int kvoff = part * 64;
    int qoff  = 64 - kvoff;

    for (int idx = t; idx < 64 * HDIM; idx += 64) {
        int m = idx / HDIM, d = idx - m * HDIM;
        ks[m * 32 + d] = base[(size_t)(kvoff + m) * C3 + CD   + h * HDIM + d];
        vs[m * 32 + d] = base[(size_t)(kvoff + m) * C3 + 2*CD + h * HDIM + d];
    }
    const float* mk = mask + (size_t)w * NMASK;   // top-left 64x64 block
    for (int idx = t; idx < 64 * 64; idx += 64) {
        int n = idx >> 6, m = idx & 63;
        sc[n * 65 + m] = mk[n * 128 + m];
    }
    __syncthreads();

    float q[HDIM];
#pragma unroll
    for (int d = 0; d < HDIM; d++)
        q[d] = base[(size_t)(qoff + t) * C3 + h * HDIM + d] * SCALE_F;

    float* srow = sc + t * 65;
    float mx = -1e30f;
    for (int m = 0; m < 64; m++) {
        const float* kr = ks + m * 32;
        float s = srow[m];
#pragma unroll
        for (int d4 = 0; d4 < 7; d4++) {
            float4 k4 = *(const float4*)(kr + d4 * 4);
            s += q[d4*4+0]*k4.x + q[d4*4+1]*k4.y + q[d4*4+2]*k4.z + q[d4*4+3]*k4.w;
        }
        s += q[28] * kr[28] + q[29] * kr[29];
        srow[m] = s;
        mx = fmaxf(mx, s);
    }
    float ssum = 0.f;
    for (int m = 0; m < 64; m++) {
        float p = __expf(srow[m] - mx);
        srow[m] = p; ssum += p;
    }
    float o[HDIM] = {};
    for (int m = 0; m < 64; m++) {
        float p = srow[m];
        const float* vr = vs + m * 32;
#pragma unroll
        for (int d4 = 0; d4 < 7; d4++) {
            float4 v4 = *(const float4*)(vr + d4 * 4);
            o[d4*4+0] += p*v4.x; o[d4*4+1] += p*v4.y;
            o[d4*4+2] += p*v4.z; o[d4*4+3] += p*v4.w;
        }
        o[28] += p * vr[28]; o[29] += p * vr[29];
    }
    float inv = 1.f / ssum;
    float* out = xo + ((size_t)(w * 128 + part * 64 + t)) * C2 + h * HDIM;
#pragma unroll
    for (int d = 0; d < HDIM; d++) out[d] = o[d] * inv;
}

// ---------------------------------------------------------------------------
extern "C" void kernel_launch(void* const* d_in, const int* in_sizes, int n_in,
                              void* d_out, int out_size) {
    const float* x          = (const float*)d_in[0];
    const float* mask       = (const float*)d_in[1];
    const float* g1         = (const float*)d_in[2];
    const float* b1         = (const float*)d_in[3];
    const float* g2         = (const float*)d_in[4];
    const float* b2         = (const float*)d_in[5];
    const float* w_qkv_self = (const float*)d_in[6];
    const float* b_qkv_self = (const float*)d_in[7];
    const float* w_qkv_mut  = (const float*)d_in[8];
    const float* b_qkv_mut  = (const float*)d_in[9];
    const float* rpb_table  = (const float*)d_in[10];
    const float* pos_bias   = (const float*)d_in[11];
    const float* w_proj     = (const float*)d_in[12];
    const float* b_proj     = (const float*)d_in[13];
    const float* w_fc11     = (const float*)d_in[14];
    const float* b_fc11     = (const float*)d_in[15];
    const float* w_fc12     = (const float*)d_in[16];
    const float* b_fc12     = (const float*)d_in[17];
    const float* w_fc2      = (const float*)d_in[18];
    const float* b_fc2      = (const float*)d_in[19];
    const int*   rpi        = (const int*)d_in[20];
    float* out = (float*)d_out;

    float *p_xw, *p_qs, *p_qm, *p_xo, *p_x1;
    cudaGetSymbolAddress((void**)&p_xw, g_xw);
    cudaGetSymbolAddress((void**)&p_qs, g_qkv_s);
    cudaGetSymbolAddress((void**)&p_qm, g_qkv_m);
    cudaGetSymbolAddress((void**)&p_xo, g_xo);
    cudaGetSymbolAddress((void**)&p_x1, g_x1);

    int attn_smem = (128 * 32 * 2 + 128 * 129) * 4;  // 98816 B
    cudaFuncSetAttribute(attn_self_kernel,
                         cudaFuncAttributeMaxDynamicSharedMemorySize, attn_smem);

    // 1) rel-pos bias gather
    bias6_kernel<<<(NHEAD * NMASK + 255) / 256, 256>>>(rpb_table, rpi);
    // 2) LN1 + roll + window partition
    ln_kernel<<<NTOK / 8, 256>>>(x, g1, b1, p_xw, 1);
    // 3) qkv_self / qkv_mut (pos_bias folded into A of mut)
    gemm64<0><<<dim3(9, NTOK / 64), 256>>>(p_xw, w_qkv_self, b_qkv_self, p_qs,
                                           NTOK, C3, CD, nullptr, nullptr);
    gemm64<0><<<dim3(9, NTOK / 64), 256>>>(p_xw, w_qkv_mut, b_qkv_mut, p_qm,
                                           NTOK, C3, CD, pos_bias, nullptr);
    // 4) attention branches -> g_xo (mut: ch 0..179, self: ch 180..359)
    attn_self_kernel<<<NWIN * NHEAD, 128, attn_smem>>>(p_qs, mask, p_xo);
    attn_mut_kernel<<<NWIN * NHEAD * 2, 64>>>(p_qm, mask, p_xo);
    // 5) proj + window reverse + unroll + residual -> g_x1
    gemm64<1><<<dim3(3, NTOK / 64), 256>>>(p_xo, w_proj, b_proj, p_x1,
                                           NTOK, CD, C2, nullptr, x);
    // 6) LN2
    ln_kernel<<<NTOK / 8, 256>>>(p_x1, g2, b2, p_xw, 0);
    // 7) GEGLU MLP: hidden = gelu(fc11) * fc12  -> g_xo
    fc1_kernel<<<dim3(6, NTOK / 64), 256>>>(p_xw, w_fc11, b_fc11, w_fc12, b_fc12,
                                            p_xo, NTOK, C2, CD);
    // 8) fc2 + residual -> out
    gemm64<3><<<dim3(3, NTOK / 64), 256>>>(p_xo, w_fc2, b_fc2, out,
                                           NTOK, CD, C2, nullptr, p_x1);
    (void)in_sizes; (void)n_in; (void)out_size;
}

// round 11
// speedup vs baseline: 2.3315x; 2.3315x over previous
#include <cuda_runtime.h>
#include <cuda_bf16.h>
#include <math.h>
#include <stdint.h>

// ---------------------------------------------------------------------------
// B=1, D=6, H=128, W=128, C=180, NH=6, HD=30, WS=(2,8,8) -> N=128/window,
// 768 windows, SS=(1,4,4), HID=360
// ---------------------------------------------------------------------------
#define NTOK   98304
#define CD     180
#define C3     540
#define C2     360
#define NWIN   768
#define NHEAD  6
#define HDIM   30
#define NMASK  16384
#define KP1    192            // padded K for C=180
#define KP2    384            // padded K for 2C=360
#define SCALE_F 0.18257418583505536f

// ------------------------- scratch (static, no alloc) ----------------------
__device__ __nv_bfloat16 g_a1 [(size_t)NTOK * KP1];   // LN1 out (bf16, padded)
__device__ __nv_bfloat16 g_a1m[(size_t)NTOK * KP1];   // LN1 out + pos_bias
__device__ __nv_bfloat16 g_qkv_s[(size_t)NTOK * C3];  // qkv self
__device__ __nv_bfloat16 g_qkv_m[(size_t)NTOK * C3];  // qkv mutual
__device__ __nv_bfloat16 g_xo  [(size_t)NTOK * KP2];  // attn concat (padded)
__device__ float         g_x1  [(size_t)NTOK * CD];   // x + attn branch
__device__ __nv_bfloat16 g_a2  [(size_t)NTOK * KP1];  // LN2 out
__device__ __nv_bfloat16 g_hid [(size_t)NTOK * KP2];  // MLP hidden (padded)
__device__ float         g_bias6[NHEAD * NMASK];
// transposed / padded bf16 weights: wT[n][k]
__device__ __nv_bfloat16 g_wqs [640 * KP1];
__device__ __nv_bfloat16 g_wqm [640 * KP1];
__device__ __nv_bfloat16 g_wpr [256 * KP2];
__device__ __nv_bfloat16 g_wmix[768 * KP1];           // interleaved fc11/fc12
__device__ __nv_bfloat16 g_wf2 [256 * KP2];

// windowed row -> global token (roll(-S) + win_part; self-inverse pairing)
__device__ __forceinline__ int win2glob(int r) {
    int w = r >> 7, n = r & 127;
    int dblk = w >> 8, hblk = (w >> 4) & 15, wblk = w & 15;
    int wd = n >> 6,  wh = (n >> 3) & 7,   ww = n & 7;
    int d = dblk * 2 + wd + 1; if (d >= 6) d -= 6;
    int hh = (hblk * 8 + wh + 4) & 127;
    int w2 = (wblk * 8 + ww + 4) & 127;
    return (d * 128 + hh) * 128 + w2;
}

__device__ __forceinline__ uint32_t smem_u32(const void* p) {
    uint32_t a;
    asm("{ .reg .u64 t; cvta.to.shared.u64 t, %1; cvt.u32.u64 %0, t; }"
        : "=r"(a) : "l"(p));
    return a;
}

#define LDMATRIX_X4(r0, r1, r2, r3, addr) \
    asm volatile("ldmatrix.sync.aligned.m8n8.x4.shared.b16 {%0,%1,%2,%3}, [%4];" \
        : "=r"(r0), "=r"(r1), "=r"(r2), "=r"(r3) : "r"(addr))

#define MMA16816(d, a, b) \
    asm volatile("mma.sync.aligned.m16n8k16.row.col.f32.bf16.bf16.f32 " \
        "{%0,%1,%2,%3}, {%4,%5,%6,%7}, {%8,%9}, {%0,%1,%2,%3};" \
        : "+f"((d)[0]), "+f"((d)[1]), "+f"((d)[2]), "+f"((d)[3]) \
        : "r"((a)[0]), "r"((a)[1]), "r"((a)[2]), "r"((a)[3]), \
          "r"((b)[0]), "r"((b)[1]))

// ------------------------- prep kernels ------------------------------------
__global__ void bias6_kernel(const float* __restrict__ rpb, const int* __restrict__ rpi) {
    int t = blockIdx.x * 256 + threadIdx.x;
    if (t < NHEAD * NMASK) {
        int h = t >> 14, nm = t & (NMASK - 1);
        g_bias6[t] = rpb[rpi[nm] * NHEAD + h];
    }
}

// dst[n][k] = src[k][n] (zero-padded), bf16
__global__ void transpose_pad(const float* __restrict__ src, __nv_bfloat16* __restrict__ dst,
                              int K, int N, int Kpad, int Nrows) {
    int idx = blockIdx.x * 256 + threadIdx.x;
    if (idx >= Nrows * Kpad) return;
    int n = idx / Kpad, k = idx - n * Kpad;
    float v = (n < N && k < K) ? src[(size_t)k * N + n] : 0.f;
    dst[idx] = __float2bfloat16(v);
}

// interleaved fc11/fc12: row r -> (r&1 ? w12 : w11) column r>>1
__global__ void mix_fc1(const float* __restrict__ w11, const float* __restrict__ w12) {
    int idx = blockIdx.x * 256 + threadIdx.x;
    if (idx >= 768 * KP1) return;
    int r = idx / KP1, k = idx - r * KP1;
    int n = r >> 1;
    float v = 0.f;
    if (k < CD && n < C2)
        v = (r & 1) ? w12[(size_t)k * C2 + n] : w11[(size_t)k * C2 + n];
    g_wmix[idx] = __float2bfloat16(v);
}

// zero pad cols 360..383 of attn-concat and MLP-hidden buffers
__global__ void pad_xo_kernel() {
    int idx = blockIdx.x * 256 + threadIdx.x;
    if (idx < NTOK * 24) {
        int r = idx / 24, c = 360 + idx % 24;
        g_xo [(size_t)r * KP2 + c] = __float2bfloat16(0.f);
        g_hid[(size_t)r * KP2 + c] = __float2bfloat16(0.f);
    }
}

// ------------------------- LayerNorms (warp/token, bf16 out) ---------------
__global__ void ln1_kernel(const float* __restrict__ x, const float* __restrict__ g,
                           const float* __restrict__ b, const float* __restrict__ pb) {
    int r = blockIdx.x * 8 + (threadIdx.x >> 5);
    int lane = threadIdx.x & 31;
    const float* xr = x + (size_t)win2glob(r) * CD;
    float vals[6], s = 0.f, s2 = 0.f;
#pragma unroll
    for (int i = 0; i < 6; i++) {
        int c = lane + i * 32;
        float v = (c < CD) ? xr[c] : 0.f;
        vals[i] = v; s += v; s2 += v * v;
    }
#pragma unroll
    for (int o = 16; o; o >>= 1) {
        s  += __shfl_xor_sync(0xffffffffu, s,  o);
        s2 += __shfl_xor_sync(0xffffffffu, s2, o);
    }
    float m = s * (1.f / CD);
    float rstd = rsqrtf(s2 * (1.f / CD) - m * m + 1e-5f);
    __nv_bfloat16* y1 = g_a1  + (size_t)r * KP1;
    __nv_bfloat16* y2 = g_a1m + (size_t)r * KP1;
    const float* pbr = pb + (size_t)(r & 63) * CD;
#pragma unroll
    for (int i = 0; i < 6; i++) {
        int c = lane + i * 32;
        if (c < CD) {
            float v = (vals[i] - m) * rstd * g[c] + b[c];
            y1[c] = __float2bfloat16(v);
            y2[c] = __float2bfloat16(v + pbr[c]);
        } else {
            y1[c] = __float2bfloat16(0.f);
            y2[c] = __float2bfloat16(0.f);
        }
    }
}

__global__ void ln2_kernel(const float* __restrict__ g, const float* __restrict__ b) {
    int r = blockIdx.x * 8 + (threadIdx.x >> 5);
    int lane = threadIdx.x & 31;
    const float* xr = g_x1 + (size_t)r * CD;
    float vals[6], s = 0.f, s2 = 0.f;
#pragma unroll
    for (int i = 0; i < 6; i++) {
        int c = lane + i * 32;
        float v = (c < CD) ? xr[c] : 0.f;
        vals[i] = v; s += v; s2 += v * v;
    }
#pragma unroll
    for (int o = 16; o; o >>= 1) {
        s  += __shfl_xor_sync(0xffffffffu, s,  o);
        s2 += __shfl_xor_sync(0xffffffffu, s2, o);
    }
    float m = s * (1.f / CD);
    float rstd = rsqrtf(s2 * (1.f / CD) - m * m + 1e-5f);
    __nv_bfloat16* y = g_a2 + (size_t)r * KP1;
#pragma unroll
    for (int i = 0; i < 6; i++) {
        int c = lane + i * 32;
        float v = (c < CD) ? (vals[i] - m) * rstd * g[c] + b[c] : 0.f;
        y[c] = __float2bfloat16(v);
    }
}

// ------------------------- mma.sync bf16 GEMM ------------------------------
// D(128x128) = A(128xK) * Bt(128xK)^T, bf16 HMMA, fp32 accum.
// 256 thr = 8 warps (2x4), warp tile 64x32, block-K 64.
// EPI 0: qkv  -> bf16 out stride 540, +bias
// EPI 1: proj -> fp32 scatter win2glob + resid + bias, N=180
// EPI 2: fc1  -> interleaved (u,v) pairs -> gelu(u)*v -> bf16 hidden stride 384
// EPI 3: fc2  -> fp32 out + resid + bias, N=180
template<int EPI>
__global__ __launch_bounds__(256) void mma_gemm(
    const __nv_bfloat16* __restrict__ A, const __nv_bfloat16* __restrict__ Bt,
    const float* __restrict__ bias, const float* __restrict__ bias2,
    float* __restrict__ outF, __nv_bfloat16* __restrict__ outH,
    const float* __restrict__ resid,
    int ldA, int K, int Nreal)
{
    __shared__ __nv_bfloat16 sA[128][72];   // pad 8: conflict-free ldmatrix
    __shared__ __nv_bfloat16 sB[128][72];
    const int tid = threadIdx.x, lane = tid & 31, wid = tid >> 5;
    const int wm = wid >> 2, wn = wid & 3;  // 2 x 4 warp grid
    const int row0 = blockIdx.y * 128, col0 = blockIdx.x * 128;

    float acc[4][4][4];
#pragma unroll
    for (int a = 0; a < 4; a++)
#pragma unroll
        for (int b = 0; b < 4; b++)
#pragma unroll
            for (int c = 0; c < 4; c++) acc[a][b][c] = 0.f;

    for (int k0 = 0; k0 < K; k0 += 64) {
        // stage A,B: 128 rows x 64 cols each, 16B units (8/row)
#pragma unroll
        for (int i = 0; i < 4; i++) {
            int u = tid + i * 256;
            int r = u >> 3, s = u & 7;
            *(uint4*)&sA[r][s * 8] =
                *(const uint4*)(A + (size_t)(row0 + r) * ldA + k0 + s * 8);
        }
#pragma unroll
        for (int i = 0; i < 4; i++) {
            int u = tid + i * 256;
            int r = u >> 3, s = u & 7;
            *(uint4*)&sB[r][s * 8] =
                *(const uint4*)(Bt + (size_t)(col0 + r) * ldA + k0 + s * 8);
        }
        __syncthreads();

#pragma unroll
        for (int ks = 0; ks < 4; ks++) {
            int kk = ks * 16;
            uint32_t af[4][4];
#pragma unroll
            for (int mt = 0; mt < 4; mt++) {
                int mr = wm * 64 + mt * 16 + (lane & 15);
                int mc = kk + ((lane >> 4) << 3);
                LDMATRIX_X4(af[mt][0], af[mt][1], af[mt][2], af[mt][3],
                            smem_u32(&sA[mr][mc]));
            }
            uint32_t bfr[4][2];
#pragma unroll
            for (int np = 0; np < 2; np++) {
                int nr = wn * 32 + np * 16 + (lane & 7) + ((lane >> 4) << 3);
                int nc = kk + (((lane >> 3) & 1) << 3);
                uint32_t r0, r1, r2, r3;
                LDMATRIX_X4(r0, r1, r2, r3, smem_u32(&sB[nr][nc]));
                bfr[np * 2][0] = r0;     bfr[np * 2][1] = r1;
                bfr[np * 2 + 1][0] = r2; bfr[np * 2 + 1][1] = r3;
            }
#pragma unroll
            for (int mt = 0; mt < 4; mt++)
#pragma unroll
                for (int nt = 0; nt < 4; nt++)
                    MMA16816(acc[mt][nt], af[mt], bfr[nt]);
        }
        __syncthreads();
    }

    // ---- epilogue: thread owns (row pair, col pair) per (mt, nt) ----
    const int mbase = row0 + wm * 64, nbase = col0 + wn * 32;
#pragma unroll
    for (int mt = 0; mt < 4; mt++) {
#pragma unroll
        for (int half = 0; half < 2; half++) {
            int rr = mbase + mt * 16 + (lane >> 2) + half * 8;
            if (EPI == 0) {
                __nv_bfloat16* o = outH + (size_t)rr * C3;
#pragma unroll
                for (int nt = 0; nt < 4; nt++) {
                    int c = nbase + nt * 8 + ((lane & 3) << 1);
                    if (c < Nreal) {
                        __nv_bfloat162 h;
                        h.x = __float2bfloat16(acc[mt][nt][half * 2]     + bias[c]);
                        h.y = __float2bfloat16(acc[mt][nt][half * 2 + 1] + bias[c + 1]);
                        *(__nv_bfloat162*)(o + c) = h;
                    }
                }
            } else if (EPI == 1 || EPI == 3) {
                int gI = (EPI == 1) ? win2glob(rr) : rr;
                float* o = outF + (size_t)gI * CD;
                const float* rs = resid + (size_t)gI * CD;
#pragma unroll
                for (int nt = 0; nt < 4; nt++) {
                    int c = nbase + nt * 8 + ((lane & 3) << 1);
                    if (c < Nreal) {
                        float2 rv = *(const float2*)(rs + c);
                        float2 ov;
                        ov.x = rv.x + acc[mt][nt][half * 2]     + bias[c];
                        ov.y = rv.y + acc[mt][nt][half * 2 + 1] + bias[c + 1];
                        *(float2*)(o + c) = ov;
                    }
                }
            } else { // EPI == 2: interleaved (u,v) -> gelu(u)*v
                __nv_bfloat16* o = outH + (size_t)rr * KP2;
#pragma unroll
                for (int nt = 0; nt < 4; nt++) {
                    int c = nbase + nt * 8 + ((lane & 3) << 1);
                    if (c < 720) {
                        int n = c >> 1;
                        float u = acc[mt][nt][half * 2]     + bias[n];
                        float v = acc[mt][nt][half * 2 + 1] + bias2[n];
                        float ge = 0.5f * u * (1.f + erff(u * 0.7071067811865475f));
                        o[n] = __float2bfloat16(ge * v);
                    }
                }
            }
        }
    }
}

// ------------------------- windowed self attention -------------------------
__global__ __launch_bounds__(128) void attn_self_kernel(const float* __restrict__ mask) {
    extern __shared__ float sm[];
    float* ks = sm;                 // 128*32
    float* vs = sm + 4096;          // 128*32
    float* sc = sm + 8192;          // 128*129
    int w = blockIdx.x / NHEAD, h = blockIdx.x % NHEAD;
    int t = threadIdx.x;
    const __nv_bfloat16* base = g_qkv_s + (size_t)w * 128 * C3;

    for (int idx = t; idx < 128 * HDIM; idx += 128) {
        int m = idx / HDIM, d = idx - m * HDIM;
        ks[m * 32 + d] = __bfloat162float(base[(size_t)m * C3 + CD   + h * HDIM + d]);
        vs[m * 32 + d] = __bfloat162float(base[(size_t)m * C3 + 2*CD + h * HDIM + d]);
    }
    const float* bi = g_bias6 + h * NMASK;
    const float* mk = mask + (size_t)w * NMASK;
    for (int idx = t; idx < NMASK; idx += 128) {
        int n = idx >> 7, m = idx & 127;
        sc[n * 129 + m] = bi[idx] + mk[idx];
    }
    __syncthreads();

    float q[HDIM];
#pragma unroll
    for (int d = 0; d < HDIM; d++)
        q[d] = __bfloat162float(base[(size_t)t * C3 + h * HDIM + d]) * SCALE_F;

    float* srow = sc + t * 129;
    float mx = -1e30f;
    for (int m = 0; m < 128; m++) {
        const float* kr = ks + m * 32;
        float s = srow[m];
#pragma unroll
        for (int d4 = 0; d4 < 7; d4++) {
            float4 k4 = *(const float4*)(kr + d4 * 4);
            s += q[d4*4+0]*k4.x + q[d4*4+1]*k4.y + q[d4*4+2]*k4.z + q[d4*4+3]*k4.w;
        }
        s += q[28] * kr[28] + q[29] * kr[29];
        srow[m] = s;
        mx = fmaxf(mx, s);
    }
    float ssum = 0.f;
    for (int m = 0; m < 128; m++) {
        float p = __expf(srow[m] - mx);
        srow[m] = p; ssum += p;
    }
    float o[HDIM] = {};
    for (int m = 0; m < 128; m++) {
        float p = srow[m];
        const float* vr = vs + m * 32;
#pragma unroll
        for (int d4 = 0; d4 < 7; d4++) {
            float4 v4 = *(const float4*)(vr + d4 * 4);
            o[d4*4+0] += p*v4.x; o[d4*4+1] += p*v4.y;
            o[d4*4+2] += p*v4.z; o[d4*4+3] += p*v4.w;
        }
        o[28] += p * vr[28]; o[29] += p * vr[29];
    }
    float inv = 1.f / ssum;
    __nv_bfloat16* out = g_xo + (size_t)(w * 128 + t) * KP2 + CD + h * HDIM;
#pragma unroll
    for (int d = 0; d < HDIM; d++) out[d] = __float2bfloat16(o[d] * inv);
}

// ------------------------- mutual attention --------------------------------
__global__ __launch_bounds__(64) void attn_mut_kernel(const float* __restrict__ mask) {
    __shared__ float ks[64 * 32];
    __shared__ float vs[64 * 32];
    __shared__ float sc[64 * 65];
    int b = blockIdx.x;
    int part = b & 1, h = (b >> 1) % NHEAD, w = b / (2 * NHEAD);
    int t = threadIdx.x;
    const __nv_bfloat16* base = g_qkv_m + (size_t)w * 128 * C3;
    int kvoff = part * 64;
    int qoff  = 64 - kvoff;

    for (int idx = t; idx < 64 * HDIM; idx += 64) {
        int m = idx / HDIM, d = idx - m * HDIM;
        ks[m * 32 + d] = __bfloat162float(base[(size_t)(kvoff + m) * C3 + CD   + h * HDIM + d]);
        vs[m * 32 + d] = __bfloat162float(base[(size_t)(kvoff + m) * C3 + 2*CD + h * HDIM + d]);
    }
    const float* mk = mask + (size_t)w * NMASK;
    for (int idx = t; idx < 64 * 64; idx += 64) {
        int n = idx >> 6, m = idx & 63;
        sc[n * 65 + m] = mk[n * 128 + m];
    }
    __syncthreads();

    float q[HDIM];
#pragma unroll
    for (int d = 0; d < HDIM; d++)
        q[d] = __bfloat162float(base[(size_t)(qoff + t) * C3 + h * HDIM + d]) * SCALE_F;

    float* srow = sc + t * 65;
    float mx = -1e30f;
    for (int m = 0; m < 64; m++) {
        const float* kr = ks + m * 32;
        float s = srow[m];
#pragma unroll
        for (int d4 = 0; d4 < 7; d4++) {
            float4 k4 = *(const float4*)(kr + d4 * 4);
            s += q[d4*4+0]*k4.x + q[d4*4+1]*k4.y + q[d4*4+2]*k4.z + q[d4*4+3]*k4.w;
        }
        s += q[28] * kr[28] + q[29] * kr[29];
        srow[m] = s;
        mx = fmaxf(mx, s);
    }
    float ssum = 0.f;
    for (int m = 0; m < 64; m++) {
        float p = __expf(srow[m] - mx);
        srow[m] = p; ssum += p;
    }
    float o[HDIM] = {};
    for (int m = 0; m < 64; m++) {
        float p = srow[m];
        const float* vr = vs + m * 32;
#pragma unroll
        for (int d4 = 0; d4 < 7; d4++) {
            float4 v4 = *(const float4*)(vr + d4 * 4);
            o[d4*4+0] += p*v4.x; o[d4*4+1] += p*v4.y;
            o[d4*4+2] += p*v4.z; o[d4*4+3] += p*v4.w;
        }
        o[28] += p * vr[28]; o[29] += p * vr[29];
    }
    float inv = 1.f / ssum;
    __nv_bfloat16* out = g_xo + (size_t)(w * 128 + part * 64 + t) * KP2 + h * HDIM;
#pragma unroll
    for (int d = 0; d < HDIM; d++) out[d] = __float2bfloat16(o[d] * inv);
}

// ---------------------------------------------------------------------------
extern "C" void kernel_launch(void* const* d_in, const int* in_sizes, int n_in,
                              void* d_out, int out_size) {
    const float* x          = (const float*)d_in[0];
    const float* mask       = (const float*)d_in[1];
    const float* g1         = (const float*)d_in[2];
    const float* b1         = (const float*)d_in[3];
    const float* g2         = (const float*)d_in[4];
    const float* b2         = (const float*)d_in[5];
    const float* w_qkv_self = (const float*)d_in[6];
    const float* b_qkv_self = (const float*)d_in[7];
    const float* w_qkv_mut  = (const float*)d_in[8];
    const float* b_qkv_mut  = (const float*)d_in[9];
    const float* rpb_table  = (const float*)d_in[10];
    const float* pos_bias   = (const float*)d_in[11];
    const float* w_proj     = (const float*)d_in[12];
    const float* b_proj     = (const float*)d_in[13];
    const float* w_fc11     = (const float*)d_in[14];
    const float* b_fc11     = (const float*)d_in[15];
    const float* w_fc12     = (const float*)d_in[16];
    const float* b_fc12     = (const float*)d_in[17];
    const float* w_fc2      = (const float*)d_in[18];
    const float* b_fc2      = (const float*)d_in[19];
    const int*   rpi        = (const int*)d_in[20];
    float* out = (float*)d_out;

    __nv_bfloat16 *p_a1, *p_a1m, *p_qs, *p_qm, *p_xo, *p_a2, *p_hid;
    __nv_bfloat16 *p_wqs, *p_wqm, *p_wpr, *p_wmix, *p_wf2;
    float *p_x1;
    cudaGetSymbolAddress((void**)&p_a1,  g_a1);
    cudaGetSymbolAddress((void**)&p_a1m, g_a1m);
    cudaGetSymbolAddress((void**)&p_qs,  g_qkv_s);
    cudaGetSymbolAddress((void**)&p_qm,  g_qkv_m);
    cudaGetSymbolAddress((void**)&p_xo,  g_xo);
    cudaGetSymbolAddress((void**)&p_a2,  g_a2);
    cudaGetSymbolAddress((void**)&p_hid, g_hid);
    cudaGetSymbolAddress((void**)&p_x1,  g_x1);
    cudaGetSymbolAddress((void**)&p_wqs, g_wqs);
    cudaGetSymbolAddress((void**)&p_wqm, g_wqm);
    cudaGetSymbolAddress((void**)&p_wpr, g_wpr);
    cudaGetSymbolAddress((void**)&p_wmix,g_wmix);
    cudaGetSymbolAddress((void**)&p_wf2, g_wf2);

    int attn_smem = (128 * 32 * 2 + 128 * 129) * 4;
    cudaFuncSetAttribute(attn_self_kernel,
                         cudaFuncAttributeMaxDynamicSharedMemorySize, attn_smem);

    // -- prep (tiny) --
    bias6_kernel<<<(NHEAD * NMASK + 255) / 256, 256>>>(rpb_table, rpi);
    transpose_pad<<<(640 * KP1 + 255) / 256, 256>>>(w_qkv_self, p_wqs, CD, C3, KP1, 640);
    transpose_pad<<<(640 * KP1 + 255) / 256, 256>>>(w_qkv_mut,  p_wqm, CD, C3, KP1, 640);
    transpose_pad<<<(256 * KP2 + 255) / 256, 256>>>(w_proj,     p_wpr, C2, CD, KP2, 256);
    transpose_pad<<<(256 * KP2 + 255) / 256, 256>>>(w_fc2,      p_wf2, C2, CD, KP2, 256);
    mix_fc1<<<(768 * KP1 + 255) / 256, 256>>>(w_fc11, w_fc12);
    pad_xo_kernel<<<(NTOK * 24 + 255) / 256, 256>>>();

    // -- LN1 + roll + window partition (bf16, +pos_bias variant) --
    ln1_kernel<<<NTOK / 8, 256>>>(x, g1, b1, pos_bias);

    // -- qkv GEMMs (mma.sync bf16) --
    mma_gemm<0><<<dim3(5, NTOK / 128), 256>>>(p_a1,  p_wqs, b_qkv_self, nullptr,
                                              nullptr, p_qs, nullptr, KP1, KP1, C3);
    mma_gemm<0><<<dim3(5, NTOK / 128), 256>>>(p_a1m, p_wqm, b_qkv_mut, nullptr,
                                              nullptr, p_qm, nullptr, KP1, KP1, C3);
    // -- attention --
    attn_self_kernel<<<NWIN * NHEAD, 128, attn_smem>>>(mask);
    attn_mut_kernel<<<NWIN * NHEAD * 2, 64>>>(mask);
    // -- proj (+win_rev+roll+resid) --
    mma_gemm<1><<<dim3(2, NTOK / 128), 256>>>(p_xo, p_wpr, b_proj, nullptr,
                                              p_x1, nullptr, x, KP2, KP2, CD);
    // -- LN2 --
    ln2_kernel<<<NTOK / 8, 256>>>(g2, b2);
    // -- fc1 (fused GEGLU, interleaved weights) --
    mma_gemm<2><<<dim3(6, NTOK / 128), 256>>>(p_a2, p_wmix, b_fc11, b_fc12,
                                              nullptr, p_hid, nullptr, KP1, KP1, 720);
    // -- fc2 + residual --
    mma_gemm<3><<<dim3(2, NTOK / 128), 256>>>(p_hid, p_wf2, b_fc2, nullptr,
                                              out, nullptr, p_x1, KP2, KP2, CD);
    (void)in_sizes; (void)n_in; (void)out_size;
}

// round 12
// speedup vs baseline: 2.4535x; 1.0523x over previous
#include <cuda_runtime.h>
#include <cuda_bf16.h>
#include <math.h>
#include <stdint.h>

// ---------------------------------------------------------------------------
// B=1, D=6, H=128, W=128, C=180, NH=6, HD=30, WS=(2,8,8) -> N=128/window,
// 768 windows, SS=(1,4,4), HID=360
// ---------------------------------------------------------------------------
#define NTOK   98304
#define CD     180
#define C3     540
#define C2     360
#define NWIN   768
#define NHEAD  6
#define HDIM   30
#define NMASK  16384
#define KP1    192            // padded K for C=180
#define KP2    384            // padded K for 2C=360
#define SCALE_F 0.18257418583505536f

// ------------------------- scratch (static, no alloc) ----------------------
__device__ __nv_bfloat16 g_a1 [(size_t)NTOK * KP1];   // LN1 out (bf16, padded)
__device__ __nv_bfloat16 g_a1m[(size_t)NTOK * KP1];   // LN1 out + pos_bias
__device__ __nv_bfloat16 g_qkv_s[(size_t)NTOK * C3];  // qkv self
__device__ __nv_bfloat16 g_qkv_m[(size_t)NTOK * C3];  // qkv mutual
__device__ __nv_bfloat16 g_xo  [(size_t)NTOK * KP2];  // attn concat (padded)
__device__ float         g_x1  [(size_t)NTOK * CD];   // x + attn branch
__device__ __nv_bfloat16 g_a2  [(size_t)NTOK * KP1];  // LN2 out
__device__ __nv_bfloat16 g_hid [(size_t)NTOK * KP2];  // MLP hidden (padded)
__device__ float         g_bias6[NHEAD * NMASK];
// transposed / padded bf16 weights: wT[n][k]
__device__ __nv_bfloat16 g_wqs [640 * KP1];
__device__ __nv_bfloat16 g_wqm [640 * KP1];
__device__ __nv_bfloat16 g_wpr [256 * KP2];
__device__ __nv_bfloat16 g_wmix[768 * KP1];           // interleaved fc11/fc12
__device__ __nv_bfloat16 g_wf2 [256 * KP2];

// windowed row -> global token (roll(-S) + win_part; self-inverse pairing)
__device__ __forceinline__ int win2glob(int r) {
    int w = r >> 7, n = r & 127;
    int dblk = w >> 8, hblk = (w >> 4) & 15, wblk = w & 15;
    int wd = n >> 6,  wh = (n >> 3) & 7,   ww = n & 7;
    int d = dblk * 2 + wd + 1; if (d >= 6) d -= 6;
    int hh = (hblk * 8 + wh + 4) & 127;
    int w2 = (wblk * 8 + ww + 4) & 127;
    return (d * 128 + hh) * 128 + w2;
}

__device__ __forceinline__ uint32_t smem_u32(const void* p) {
    uint32_t a;
    asm("{ .reg .u64 t; cvta.to.shared.u64 t, %1; cvt.u32.u64 %0, t; }"
        : "=r"(a) : "l"(p));
    return a;
}

#define LDMATRIX_X4(r0, r1, r2, r3, addr) \
    asm volatile("ldmatrix.sync.aligned.m8n8.x4.shared.b16 {%0,%1,%2,%3}, [%4];" \
        : "=r"(r0), "=r"(r1), "=r"(r2), "=r"(r3) : "r"(addr))

#define MMA16816(d, a, b) \
    asm volatile("mma.sync.aligned.m16n8k16.row.col.f32.bf16.bf16.f32 " \
        "{%0,%1,%2,%3}, {%4,%5,%6,%7}, {%8,%9}, {%0,%1,%2,%3};" \
        : "+f"((d)[0]), "+f"((d)[1]), "+f"((d)[2]), "+f"((d)[3]) \
        : "r"((a)[0]), "r"((a)[1]), "r"((a)[2]), "r"((a)[3]), \
          "r"((b)[0]), "r"((b)[1]))

#define CP_ASYNC16(dst, src) \
    asm volatile("cp.async.cg.shared.global [%0], [%1], 16;" :: "r"(dst), "l"(src))
#define CP_COMMIT() asm volatile("cp.async.commit_group;")
#define CP_WAIT0()  asm volatile("cp.async.wait_group 0;")

// ------------------------- prep kernels ------------------------------------
__global__ void bias6_kernel(const float* __restrict__ rpb, const int* __restrict__ rpi) {
    int t = blockIdx.x * 256 + threadIdx.x;
    if (t < NHEAD * NMASK) {
        int h = t >> 14, nm = t & (NMASK - 1);
        g_bias6[t] = rpb[rpi[nm] * NHEAD + h];
    }
}

// dst[n][k] = src[k][n] (zero-padded), bf16
__global__ void transpose_pad(const float* __restrict__ src, __nv_bfloat16* __restrict__ dst,
                              int K, int N, int Kpad, int Nrows) {
    int idx = blockIdx.x * 256 + threadIdx.x;
    if (idx >= Nrows * Kpad) return;
    int n = idx / Kpad, k = idx - n * Kpad;
    float v = (n < N && k < K) ? src[(size_t)k * N + n] : 0.f;
    dst[idx] = __float2bfloat16(v);
}

// interleaved fc11/fc12: row r -> (r&1 ? w12 : w11) column r>>1
__global__ void mix_fc1(const float* __restrict__ w11, const float* __restrict__ w12) {
    int idx = blockIdx.x * 256 + threadIdx.x;
    if (idx >= 768 * KP1) return;
    int r = idx / KP1, k = idx - r * KP1;
    int n = r >> 1;
    float v = 0.f;
    if (k < CD && n < C2)
        v = (r & 1) ? w12[(size_t)k * C2 + n] : w11[(size_t)k * C2 + n];
    g_wmix[idx] = __float2bfloat16(v);
}

// zero pad cols 360..383 of attn-concat and MLP-hidden buffers
__global__ void pad_xo_kernel() {
    int idx = blockIdx.x * 256 + threadIdx.x;
    if (idx < NTOK * 24) {
        int r = idx / 24, c = 360 + idx % 24;
        g_xo [(size_t)r * KP2 + c] = __float2bfloat16(0.f);
        g_hid[(size_t)r * KP2 + c] = __float2bfloat16(0.f);
    }
}

// ------------------------- LayerNorms (warp/token, bf16 out) ---------------
__global__ void ln1_kernel(const float* __restrict__ x, const float* __restrict__ g,
                           const float* __restrict__ b, const float* __restrict__ pb) {
    int r = blockIdx.x * 8 + (threadIdx.x >> 5);
    int lane = threadIdx.x & 31;
    const float* xr = x + (size_t)win2glob(r) * CD;
    float vals[6], s = 0.f, s2 = 0.f;
#pragma unroll
    for (int i = 0; i < 6; i++) {
        int c = lane + i * 32;
        float v = (c < CD) ? xr[c] : 0.f;
        vals[i] = v; s += v; s2 += v * v;
    }
#pragma unroll
    for (int o = 16; o; o >>= 1) {
        s  += __shfl_xor_sync(0xffffffffu, s,  o);
        s2 += __shfl_xor_sync(0xffffffffu, s2, o);
    }
    float m = s * (1.f / CD);
    float rstd = rsqrtf(s2 * (1.f / CD) - m * m + 1e-5f);
    __nv_bfloat16* y1 = g_a1  + (size_t)r * KP1;
    __nv_bfloat16* y2 = g_a1m + (size_t)r * KP1;
    const float* pbr = pb + (size_t)(r & 63) * CD;
#pragma unroll
    for (int i = 0; i < 6; i++) {
        int c = lane + i * 32;
        if (c < CD) {
            float v = (vals[i] - m) * rstd * g[c] + b[c];
            y1[c] = __float2bfloat16(v);
            y2[c] = __float2bfloat16(v + pbr[c]);
        } else {
            y1[c] = __float2bfloat16(0.f);
            y2[c] = __float2bfloat16(0.f);
        }
    }
}

__global__ void ln2_kernel(const float* __restrict__ g, const float* __restrict__ b) {
    int r = blockIdx.x * 8 + (threadIdx.x >> 5);
    int lane = threadIdx.x & 31;
    const float* xr = g_x1 + (size_t)r * CD;
    float vals[6], s = 0.f, s2 = 0.f;
#pragma unroll
    for (int i = 0; i < 6; i++) {
        int c = lane + i * 32;
        float v = (c < CD) ? xr[c] : 0.f;
        vals[i] = v; s += v; s2 += v * v;
    }
#pragma unroll
    for (int o = 16; o; o >>= 1) {
        s  += __shfl_xor_sync(0xffffffffu, s,  o);
        s2 += __shfl_xor_sync(0xffffffffu, s2, o);
    }
    float m = s * (1.f / CD);
    float rstd = rsqrtf(s2 * (1.f / CD) - m * m + 1e-5f);
    __nv_bfloat16* y = g_a2 + (size_t)r * KP1;
#pragma unroll
    for (int i = 0; i < 6; i++) {
        int c = lane + i * 32;
        float v = (c < CD) ? (vals[i] - m) * rstd * g[c] + b[c] : 0.f;
        y[c] = __float2bfloat16(v);
    }
}

// ------------------------- mma.sync bf16 GEMM (cp.async pipelined) ---------
// D(128x128) = A(128xK) * Bt(128xK)^T, bf16 HMMA, fp32 accum.
// 256 thr = 8 warps (2x4), warp tile 64x32, block-K 64, double-buffered
// cp.async staging (loads for chunk c+1 overlap MMA of chunk c).
// Dynamic smem: A[2][128][72] then B[2][128][72] bf16 = 73728 B.
// EPI 0: qkv  -> bf16 out stride 540, +bias
// EPI 1: proj -> fp32 scatter win2glob + resid + bias, N=180
// EPI 2: fc1  -> interleaved (u,v) pairs -> gelu(u)*v -> bf16 hidden stride 384
// EPI 3: fc2  -> fp32 out + resid + bias, N=180
#define SBUF 9216   // halves per buffer (128*72)
template<int EPI>
__global__ __launch_bounds__(256) void mma_gemm(
    const __nv_bfloat16* __restrict__ A, const __nv_bfloat16* __restrict__ Bt,
    const float* __restrict__ bias, const float* __restrict__ bias2,
    float* __restrict__ outF, __nv_bfloat16* __restrict__ outH,
    const float* __restrict__ resid,
    int ldA, int K, int Nreal)
{
    extern __shared__ __align__(16) __nv_bfloat16 smp[];
    const int tid = threadIdx.x, lane = tid & 31, wid = tid >> 5;
    const int wm = wid >> 2, wn = wid & 3;  // 2 x 4 warp grid
    const int row0 = blockIdx.y * 128, col0 = blockIdx.x * 128;

    float acc[4][4][4];
#pragma unroll
    for (int a = 0; a < 4; a++)
#pragma unroll
        for (int b = 0; b < 4; b++)
#pragma unroll
            for (int c = 0; c < 4; c++) acc[a][b][c] = 0.f;

    // stage chunk k0 into buffer buf (A and B tiles, 16B per lane per iter)
    auto stage = [&](int buf, int k0) {
        __nv_bfloat16* dA = smp + buf * SBUF;
        __nv_bfloat16* dB = smp + 2 * SBUF + buf * SBUF;
#pragma unroll
        for (int i = 0; i < 4; i++) {
            int u = tid + i * 256;
            int r = u >> 3, s = u & 7;
            CP_ASYNC16(smem_u32(dA + r * 72 + s * 8),
                       A + (size_t)(row0 + r) * ldA + k0 + s * 8);
            CP_ASYNC16(smem_u32(dB + r * 72 + s * 8),
                       Bt + (size_t)(col0 + r) * ldA + k0 + s * 8);
        }
    };

    const int nC = K / 64;
    stage(0, 0);
    CP_COMMIT();

    for (int c = 0; c < nC; c++) {
        CP_WAIT0();
        __syncthreads();
        if (c + 1 < nC) { stage((c + 1) & 1, (c + 1) * 64); CP_COMMIT(); }

        __nv_bfloat16 (*sA)[72] = (__nv_bfloat16(*)[72])(smp + (c & 1) * SBUF);
        __nv_bfloat16 (*sB)[72] = (__nv_bfloat16(*)[72])(smp + 2 * SBUF + (c & 1) * SBUF);

#pragma unroll
        for (int ks = 0; ks < 4; ks++) {
            int kk = ks * 16;
            uint32_t af[4][4];
#pragma unroll
            for (int mt = 0; mt < 4; mt++) {
                int mr = wm * 64 + mt * 16 + (lane & 15);
                int mc = kk + ((lane >> 4) << 3);
                LDMATRIX_X4(af[mt][0], af[mt][1], af[mt][2], af[mt][3],
                            smem_u32(&sA[mr][mc]));
            }
            uint32_t bfr[4][2];
#pragma unroll
            for (int np = 0; np < 2; np++) {
                int nr = wn * 32 + np * 16 + (lane & 7) + ((lane >> 4) << 3);
                int nc = kk + (((lane >> 3) & 1) << 3);
                uint32_t r0, r1, r2, r3;
                LDMATRIX_X4(r0, r1, r2, r3, smem_u32(&sB[nr][nc]));
                bfr[np * 2][0] = r0;     bfr[np * 2][1] = r1;
                bfr[np * 2 + 1][0] = r2; bfr[np * 2 + 1][1] = r3;
            }
#pragma unroll
            for (int mt = 0; mt < 4; mt++)
#pragma unroll
                for (int nt = 0; nt < 4; nt++)
                    MMA16816(acc[mt][nt], af[mt], bfr[nt]);
        }
        __syncthreads();
    }

    // ---- epilogue: thread owns (row pair, col pair) per (mt, nt) ----
    const int mbase = row0 + wm * 64, nbase = col0 + wn * 32;
#pragma unroll
    for (int mt = 0; mt < 4; mt++) {
#pragma unroll
        for (int half = 0; half < 2; half++) {
            int rr = mbase + mt * 16 + (lane >> 2) + half * 8;
            if (EPI == 0) {
                __nv_bfloat16* o = outH + (size_t)rr * C3;
#pragma unroll
                for (int nt = 0; nt < 4; nt++) {
                    int c = nbase + nt * 8 + ((lane & 3) << 1);
                    if (c < Nreal) {
                        __nv_bfloat162 h;
                        h.x = __float2bfloat16(acc[mt][nt][half * 2]     + bias[c]);
                        h.y = __float2bfloat16(acc[mt][nt][half * 2 + 1] + bias[c + 1]);
                        *(__nv_bfloat162*)(o + c) = h;
                    }
                }
            } else if (EPI == 1 || EPI == 3) {
                int gI = (EPI == 1) ? win2glob(rr) : rr;
                float* o = outF + (size_t)gI * CD;
                const float* rs = resid + (size_t)gI * CD;
#pragma unroll
                for (int nt = 0; nt < 4; nt++) {
                    int c = nbase + nt * 8 + ((lane & 3) << 1);
                    if (c < Nreal) {
                        float2 rv = *(const float2*)(rs + c);
                        float2 ov;
                        ov.x = rv.x + acc[mt][nt][half * 2]     + bias[c];
                        ov.y = rv.y + acc[mt][nt][half * 2 + 1] + bias[c + 1];
                        *(float2*)(o + c) = ov;
                    }
                }
            } else { // EPI == 2: interleaved (u,v) -> gelu(u)*v
                __nv_bfloat16* o = outH + (size_t)rr * KP2;
#pragma unroll
                for (int nt = 0; nt < 4; nt++) {
                    int c = nbase + nt * 8 + ((lane & 3) << 1);
                    if (c < 720) {
                        int n = c >> 1;
                        float u = acc[mt][nt][half * 2]     + bias[n];
                        float v = acc[mt][nt][half * 2 + 1] + bias2[n];
                        float ge = 0.5f * u * (1.f + erff(u * 0.7071067811865475f));
                        o[n] = __float2bfloat16(ge * v);
                    }
                }
            }
        }
    }
}

// ------------------------- windowed self attention -------------------------
__global__ __launch_bounds__(128) void attn_self_kernel(const float* __restrict__ mask) {
    extern __shared__ float sm[];
    float* ks = sm;                 // 128*32
    float* vs = sm + 4096;          // 128*32
    float* sc = sm + 8192;          // 128*129
    int w = blockIdx.x / NHEAD, h = blockIdx.x % NHEAD;
    int t = threadIdx.x;
    const __nv_bfloat16* base = g_qkv_s + (size_t)w * 128 * C3;

    for (int idx = t; idx < 128 * HDIM; idx += 128) {
        int m = idx / HDIM, d = idx - m * HDIM;
        ks[m * 32 + d] = __bfloat162float(base[(size_t)m * C3 + CD   + h * HDIM + d]);
        vs[m * 32 + d] = __bfloat162float(base[(size_t)m * C3 + 2*CD + h * HDIM + d]);
    }
    const float* bi = g_bias6 + h * NMASK;
    const float* mk = mask + (size_t)w * NMASK;
    for (int idx = t; idx < NMASK; idx += 128) {
        int n = idx >> 7, m = idx & 127;
        sc[n * 129 + m] = bi[idx] + mk[idx];
    }
    __syncthreads();

    float q[HDIM];
#pragma unroll
    for (int d = 0; d < HDIM; d++)
        q[d] = __bfloat162float(base[(size_t)t * C3 + h * HDIM + d]) * SCALE_F;

    float* srow = sc + t * 129;
    float mx = -1e30f;
    for (int m = 0; m < 128; m++) {
        const float* kr = ks + m * 32;
        float s = srow[m];
#pragma unroll
        for (int d4 = 0; d4 < 7; d4++) {
            float4 k4 = *(const float4*)(kr + d4 * 4);
            s += q[d4*4+0]*k4.x + q[d4*4+1]*k4.y + q[d4*4+2]*k4.z + q[d4*4+3]*k4.w;
        }
        s += q[28] * kr[28] + q[29] * kr[29];
        srow[m] = s;
        mx = fmaxf(mx, s);
    }
    float ssum = 0.f;
    for (int m = 0; m < 128; m++) {
        float p = __expf(srow[m] - mx);
        srow[m] = p; ssum += p;
    }
    float o[HDIM] = {};
    for (int m = 0; m < 128; m++) {
        float p = srow[m];
        const float* vr = vs + m * 32;
#pragma unroll
        for (int d4 = 0; d4 < 7; d4++) {
            float4 v4 = *(const float4*)(vr + d4 * 4);
            o[d4*4+0] += p*v4.x; o[d4*4+1] += p*v4.y;
            o[d4*4+2] += p*v4.z; o[d4*4+3] += p*v4.w;
        }
        o[28] += p * vr[28]; o[29] += p * vr[29];
    }
    float inv = 1.f / ssum;
    __nv_bfloat16* out = g_xo + (size_t)(w * 128 + t) * KP2 + CD + h * HDIM;
#pragma unroll
    for (int d = 0; d < HDIM; d++) out[d] = __float2bfloat16(o[d] * inv);
}

// ------------------------- mutual attention --------------------------------
__global__ __launch_bounds__(64) void attn_mut_kernel(const float* __restrict__ mask) {
    __shared__ float ks[64 * 32];
    __shared__ float vs[64 * 32];
    __shared__ float sc[64 * 65];
    int b = blockIdx.x;
    int part = b & 1, h = (b >> 1) % NHEAD, w = b / (2 * NHEAD);
    int t = threadIdx.x;
    const __nv_bfloat16* base = g_qkv_m + (size_t)w * 128 * C3;
    int kvoff = part * 64;
    int qoff  = 64 - kvoff;

    for (int idx = t; idx < 64 * HDIM; idx += 64) {
        int m = idx / HDIM, d = idx - m * HDIM;
        ks[m * 32 + d] = __bfloat162float(base[(size_t)(kvoff + m) * C3 + CD   + h * HDIM + d]);
        vs[m * 32 + d] = __bfloat162float(base[(size_t)(kvoff + m) * C3 + 2*CD + h * HDIM + d]);
    }
    const float* mk = mask + (size_t)w * NMASK;
    for (int idx = t; idx < 64 * 64; idx += 64) {
        int n = idx >> 6, m = idx & 63;
        sc[n * 65 + m] = mk[n * 128 + m];
    }
    __syncthreads();

    float q[HDIM];
#pragma unroll
    for (int d = 0; d < HDIM; d++)
        q[d] = __bfloat162float(base[(size_t)(qoff + t) * C3 + h * HDIM + d]) * SCALE_F;

    float* srow = sc + t * 65;
    float mx = -1e30f;
    for (int m = 0; m < 64; m++) {
        const float* kr = ks + m * 32;
        float s = srow[m];
#pragma unroll
        for (int d4 = 0; d4 < 7; d4++) {
            float4 k4 = *(const float4*)(kr + d4 * 4);
            s += q[d4*4+0]*k4.x + q[d4*4+1]*k4.y + q[d4*4+2]*k4.z + q[d4*4+3]*k4.w;
        }
        s += q[28] * kr[28] + q[29] * kr[29];
        srow[m] = s;
        mx = fmaxf(mx, s);
    }
    float ssum = 0.f;
    for (int m = 0; m < 64; m++) {
        float p = __expf(srow[m] - mx);
        srow[m] = p; ssum += p;
    }
    float o[HDIM] = {};
    for (int m = 0; m < 64; m++) {
        float p = srow[m];
        const float* vr = vs + m * 32;
#pragma unroll
        for (int d4 = 0; d4 < 7; d4++) {
            float4 v4 = *(const float4*)(vr + d4 * 4);
            o[d4*4+0] += p*v4.x; o[d4*4+1] += p*v4.y;
            o[d4*4+2] += p*v4.z; o[d4*4+3] += p*v4.w;
        }
        o[28] += p * vr[28]; o[29] += p * vr[29];
    }
    float inv = 1.f / ssum;
    __nv_bfloat16* out = g_xo + (size_t)(w * 128 + part * 64 + t) * KP2 + h * HDIM;
#pragma unroll
    for (int d = 0; d < HDIM; d++) out[d] = __float2bfloat16(o[d] * inv);
}

// ---------------------------------------------------------------------------
extern "C" void kernel_launch(void* const* d_in, const int* in_sizes, int n_in,
                              void* d_out, int out_size) {
    const float* x          = (const float*)d_in[0];
    const float* mask       = (const float*)d_in[1];
    const float* g1         = (const float*)d_in[2];
    const float* b1         = (const float*)d_in[3];
    const float* g2         = (const float*)d_in[4];
    const float* b2         = (const float*)d_in[5];
    const float* w_qkv_self = (const float*)d_in[6];
    const float* b_qkv_self = (const float*)d_in[7];
    const float* w_qkv_mut  = (const float*)d_in[8];
    const float* b_qkv_mut  = (const float*)d_in[9];
    const float* rpb_table  = (const float*)d_in[10];
    const float* pos_bias   = (const float*)d_in[11];
    const float* w_proj     = (const float*)d_in[12];
    const float* b_proj     = (const float*)d_in[13];
    const float* w_fc11     = (const float*)d_in[14];
    const float* b_fc11     = (const float*)d_in[15];
    const float* w_fc12     = (const float*)d_in[16];
    const float* b_fc12     = (const float*)d_in[17];
    const float* w_fc2      = (const float*)d_in[18];
    const float* b_fc2      = (const float*)d_in[19];
    const int*   rpi        = (const int*)d_in[20];
    float* out = (float*)d_out;

    __nv_bfloat16 *p_a1, *p_a1m, *p_qs, *p_qm, *p_xo, *p_a2, *p_hid;
    __nv_bfloat16 *p_wqs, *p_wqm, *p_wpr, *p_wmix, *p_wf2;
    float *p_x1;
    cudaGetSymbolAddress((void**)&p_a1,  g_a1);
    cudaGetSymbolAddress((void**)&p_a1m, g_a1m);
    cudaGetSymbolAddress((void**)&p_qs,  g_qkv_s);
    cudaGetSymbolAddress((void**)&p_qm,  g_qkv_m);
    cudaGetSymbolAddress((void**)&p_xo,  g_xo);
    cudaGetSymbolAddress((void**)&p_a2,  g_a2);
    cudaGetSymbolAddress((void**)&p_hid, g_hid);
    cudaGetSymbolAddress((void**)&p_x1,  g_x1);
    cudaGetSymbolAddress((void**)&p_wqs, g_wqs);
    cudaGetSymbolAddress((void**)&p_wqm, g_wqm);
    cudaGetSymbolAddress((void**)&p_wpr, g_wpr);
    cudaGetSymbolAddress((void**)&p_wmix,g_wmix);
    cudaGetSymbolAddress((void**)&p_wf2, g_wf2);

    int attn_smem = (128 * 32 * 2 + 128 * 129) * 4;
    cudaFuncSetAttribute(attn_self_kernel,
                         cudaFuncAttributeMaxDynamicSharedMemorySize, attn_smem);

    int gemm_smem = 4 * SBUF * 2;   // 73728 B (A[2] + B[2])
    cudaFuncSetAttribute(mma_gemm<0>, cudaFuncAttributeMaxDynamicSharedMemorySize, gemm_smem);
    cudaFuncSetAttribute(mma_gemm<1>, cudaFuncAttributeMaxDynamicSharedMemorySize, gemm_smem);
    cudaFuncSetAttribute(mma_gemm<2>, cudaFuncAttributeMaxDynamicSharedMemorySize, gemm_smem);
    cudaFuncSetAttribute(mma_gemm<3>, cudaFuncAttributeMaxDynamicSharedMemorySize, gemm_smem);

    // -- prep (tiny) --
    bias6_kernel<<<(NHEAD * NMASK + 255) / 256, 256>>>(rpb_table, rpi);
    transpose_pad<<<(640 * KP1 + 255) / 256, 256>>>(w_qkv_self, p_wqs, CD, C3, KP1, 640);
    transpose_pad<<<(640 * KP1 + 255) / 256, 256>>>(w_qkv_mut,  p_wqm, CD, C3, KP1, 640);
    transpose_pad<<<(256 * KP2 + 255) / 256, 256>>>(w_proj,     p_wpr, C2, CD, KP2, 256);
    transpose_pad<<<(256 * KP2 + 255) / 256, 256>>>(w_fc2,      p_wf2, C2, CD, KP2, 256);
    mix_fc1<<<(768 * KP1 + 255) / 256, 256>>>(w_fc11, w_fc12);
    pad_xo_kernel<<<(NTOK * 24 + 255) / 256, 256>>>();

    // -- LN1 + roll + window partition (bf16, +pos_bias variant) --
    ln1_kernel<<<NTOK / 8, 256>>>(x, g1, b1, pos_bias);

    // -- qkv GEMMs (mma.sync bf16, pipelined) --
    mma_gemm<0><<<dim3(5, NTOK / 128), 256, gemm_smem>>>(p_a1,  p_wqs, b_qkv_self, nullptr,
                                              nullptr, p_qs, nullptr, KP1, KP1, C3);
    mma_gemm<0><<<dim3(5, NTOK / 128), 256, gemm_smem>>>(p_a1m, p_wqm, b_qkv_mut, nullptr,
                                              nullptr, p_qm, nullptr, KP1, KP1, C3);
    // -- attention --
    attn_self_kernel<<<NWIN * NHEAD, 128, attn_smem>>>(mask);
    attn_mut_kernel<<<NWIN * NHEAD * 2, 64>>>(mask);
    // -- proj (+win_rev+roll+resid) --
    mma_gemm<1><<<dim3(2, NTOK / 128), 256, gemm_smem>>>(p_xo, p_wpr, b_proj, nullptr,
                                              p_x1, nullptr, x, KP2, KP2, CD);
    // -- LN2 --
    ln2_kernel<<<NTOK / 8, 256>>>(g2, b2);
    // -- fc1 (fused GEGLU, interleaved weights) --
    mma_gemm<2><<<dim3(6, NTOK / 128), 256, gemm_smem>>>(p_a2, p_wmix, b_fc11, b_fc12,
                                              nullptr, p_hid, nullptr, KP1, KP1, 720);
    // -- fc2 + residual --
    mma_gemm<3><<<dim3(2, NTOK / 128), 256, gemm_smem>>>(p_hid, p_wf2, b_fc2, nullptr,
                                              out, nullptr, p_x1, KP2, KP2, CD);
    (void)in_sizes; (void)n_in; (void)out_size;
}

// round 13
// speedup vs baseline: 3.1680x; 1.2912x over previous
#include <cuda_runtime.h>
#include <cuda_bf16.h>
#include <math.h>
#include <stdint.h>

// ---------------------------------------------------------------------------
// B=1, D=6, H=128, W=128, C=180, NH=6, HD=30, WS=(2,8,8) -> N=128/window,
// 768 windows, SS=(1,4,4), HID=360
// ---------------------------------------------------------------------------
#define NTOK   98304
#define CD     180
#define C3     540
#define C2     360
#define NWIN   768
#define NHEAD  6
#define HDIM   30
#define NMASK  16384
#define KP1    192
#define KP2    384
#define SCALE_F 0.18257418583505536f

// ------------------------- scratch (static, no alloc) ----------------------
__device__ __nv_bfloat16 g_a1 [(size_t)NTOK * KP1];
__device__ __nv_bfloat16 g_a1m[(size_t)NTOK * KP1];
__device__ __nv_bfloat16 g_qkv_s[(size_t)NTOK * C3];
__device__ __nv_bfloat16 g_qkv_m[(size_t)NTOK * C3];
__device__ __nv_bfloat16 g_xo  [(size_t)NTOK * KP2];
__device__ float         g_x1  [(size_t)NTOK * CD];
__device__ __nv_bfloat16 g_a2  [(size_t)NTOK * KP1];
__device__ __nv_bfloat16 g_hid [(size_t)NTOK * KP2];
__device__ float         g_bias6[NHEAD * NMASK];
__device__ __nv_bfloat16 g_wqs [640 * KP1];
__device__ __nv_bfloat16 g_wqm [640 * KP1];
__device__ __nv_bfloat16 g_wpr [256 * KP2];
__device__ __nv_bfloat16 g_wmix[768 * KP1];
__device__ __nv_bfloat16 g_wf2 [256 * KP2];

__device__ __forceinline__ int win2glob(int r) {
    int w = r >> 7, n = r & 127;
    int dblk = w >> 8, hblk = (w >> 4) & 15, wblk = w & 15;
    int wd = n >> 6,  wh = (n >> 3) & 7,   ww = n & 7;
    int d = dblk * 2 + wd + 1; if (d >= 6) d -= 6;
    int hh = (hblk * 8 + wh + 4) & 127;
    int w2 = (wblk * 8 + ww + 4) & 127;
    return (d * 128 + hh) * 128 + w2;
}

__device__ __forceinline__ uint32_t smem_u32(const void* p) {
    uint32_t a;
    asm("{ .reg .u64 t; cvta.to.shared.u64 t, %1; cvt.u32.u64 %0, t; }"
        : "=r"(a) : "l"(p));
    return a;
}

#define LDMATRIX_X4(r0, r1, r2, r3, addr) \
    asm volatile("ldmatrix.sync.aligned.m8n8.x4.shared.b16 {%0,%1,%2,%3}, [%4];" \
        : "=r"(r0), "=r"(r1), "=r"(r2), "=r"(r3) : "r"(addr))

#define MMA16816(d, a, b) \
    asm volatile("mma.sync.aligned.m16n8k16.row.col.f32.bf16.bf16.f32 " \
        "{%0,%1,%2,%3}, {%4,%5,%6,%7}, {%8,%9}, {%0,%1,%2,%3};" \
        : "+f"((d)[0]), "+f"((d)[1]), "+f"((d)[2]), "+f"((d)[3]) \
        : "r"((a)[0]), "r"((a)[1]), "r"((a)[2]), "r"((a)[3]), \
          "r"((b)[0]), "r"((b)[1]))

#define CP_ASYNC16(dst, src) \
    asm volatile("cp.async.cg.shared.global [%0], [%1], 16;" :: "r"(dst), "l"(src))
#define CP_COMMIT() asm volatile("cp.async.commit_group;")
#define CP_WAIT0()  asm volatile("cp.async.wait_group 0;")
#define CP_WAIT1()  asm volatile("cp.async.wait_group 1;")

// ------------------------- prep kernels ------------------------------------
__global__ void bias6_kernel(const float* __restrict__ rpb, const int* __restrict__ rpi) {
    int t = blockIdx.x * 256 + threadIdx.x;
    if (t < NHEAD * NMASK) {
        int h = t >> 14, nm = t & (NMASK - 1);
        g_bias6[t] = rpb[rpi[nm] * NHEAD + h];
    }
}

__global__ void transpose_pad(const float* __restrict__ src, __nv_bfloat16* __restrict__ dst,
                              int K, int N, int Kpad, int Nrows) {
    int idx = blockIdx.x * 256 + threadIdx.x;
    if (idx >= Nrows * Kpad) return;
    int n = idx / Kpad, k = idx - n * Kpad;
    float v = (n < N && k < K) ? src[(size_t)k * N + n] : 0.f;
    dst[idx] = __float2bfloat16(v);
}

__global__ void mix_fc1(const float* __restrict__ w11, const float* __restrict__ w12) {
    int idx = blockIdx.x * 256 + threadIdx.x;
    if (idx >= 768 * KP1) return;
    int r = idx / KP1, k = idx - r * KP1;
    int n = r >> 1;
    float v = 0.f;
    if (k < CD && n < C2)
        v = (r & 1) ? w12[(size_t)k * C2 + n] : w11[(size_t)k * C2 + n];
    g_wmix[idx] = __float2bfloat16(v);
}

__global__ void pad_xo_kernel() {
    int idx = blockIdx.x * 256 + threadIdx.x;
    if (idx < NTOK * 24) {
        int r = idx / 24, c = 360 + idx % 24;
        g_xo [(size_t)r * KP2 + c] = __float2bfloat16(0.f);
        g_hid[(size_t)r * KP2 + c] = __float2bfloat16(0.f);
    }
}

// ------------------------- LayerNorms (warp/token, bf16 out) ---------------
__global__ void ln1_kernel(const float* __restrict__ x, const float* __restrict__ g,
                           const float* __restrict__ b, const float* __restrict__ pb) {
    int r = blockIdx.x * 8 + (threadIdx.x >> 5);
    int lane = threadIdx.x & 31;
    const float* xr = x + (size_t)win2glob(r) * CD;
    float vals[6], s = 0.f, s2 = 0.f;
#pragma unroll
    for (int i = 0; i < 6; i++) {
        int c = lane + i * 32;
        float v = (c < CD) ? xr[c] : 0.f;
        vals[i] = v; s += v; s2 += v * v;
    }
#pragma unroll
    for (int o = 16; o; o >>= 1) {
        s  += __shfl_xor_sync(0xffffffffu, s,  o);
        s2 += __shfl_xor_sync(0xffffffffu, s2, o);
    }
    float m = s * (1.f / CD);
    float rstd = rsqrtf(s2 * (1.f / CD) - m * m + 1e-5f);
    __nv_bfloat16* y1 = g_a1  + (size_t)r * KP1;
    __nv_bfloat16* y2 = g_a1m + (size_t)r * KP1;
    const float* pbr = pb + (size_t)(r & 63) * CD;
#pragma unroll
    for (int i = 0; i < 6; i++) {
        int c = lane + i * 32;
        if (c < CD) {
            float v = (vals[i] - m) * rstd * g[c] + b[c];
            y1[c] = __float2bfloat16(v);
            y2[c] = __float2bfloat16(v + pbr[c]);
        } else {
            y1[c] = __float2bfloat16(0.f);
            y2[c] = __float2bfloat16(0.f);
        }
    }
}

__global__ void ln2_kernel(const float* __restrict__ g, const float* __restrict__ b) {
    int r = blockIdx.x * 8 + (threadIdx.x >> 5);
    int lane = threadIdx.x & 31;
    const float* xr = g_x1 + (size_t)r * CD;
    float vals[6], s = 0.f, s2 = 0.f;
#pragma unroll
    for (int i = 0; i < 6; i++) {
        int c = lane + i * 32;
        float v = (c < CD) ? xr[c] : 0.f;
        vals[i] = v; s += v; s2 += v * v;
    }
#pragma unroll
    for (int o = 16; o; o >>= 1) {
        s  += __shfl_xor_sync(0xffffffffu, s,  o);
        s2 += __shfl_xor_sync(0xffffffffu, s2, o);
    }
    float m = s * (1.f / CD);
    float rstd = rsqrtf(s2 * (1.f / CD) - m * m + 1e-5f);
    __nv_bfloat16* y = g_a2 + (size_t)r * KP1;
#pragma unroll
    for (int i = 0; i < 6; i++) {
        int c = lane + i * 32;
        float v = (c < CD) ? (vals[i] - m) * rstd * g[c] + b[c] : 0.f;
        y[c] = __float2bfloat16(v);
    }
}

// ------------------------- mma.sync bf16 GEMM (cp.async pipelined) ---------
#define SBUF 9216   // halves per buffer (128*72)
template<int EPI>
__global__ __launch_bounds__(256) void mma_gemm(
    const __nv_bfloat16* __restrict__ A, const __nv_bfloat16* __restrict__ Bt,
    const float* __restrict__ bias, const float* __restrict__ bias2,
    float* __restrict__ outF, __nv_bfloat16* __restrict__ outH,
    const float* __restrict__ resid,
    int ldA, int K, int Nreal)
{
    extern __shared__ __align__(16) __nv_bfloat16 smp[];
    const int tid = threadIdx.x, lane = tid & 31, wid = tid >> 5;
    const int wm = wid >> 2, wn = wid & 3;
    const int row0 = blockIdx.y * 128, col0 = blockIdx.x * 128;

    float acc[4][4][4];
#pragma unroll
    for (int a = 0; a < 4; a++)
#pragma unroll
        for (int b = 0; b < 4; b++)
#pragma unroll
            for (int c = 0; c < 4; c++) acc[a][b][c] = 0.f;

    auto stage = [&](int buf, int k0) {
        __nv_bfloat16* dA = smp + buf * SBUF;
        __nv_bfloat16* dB = smp + 2 * SBUF + buf * SBUF;
#pragma unroll
        for (int i = 0; i < 4; i++) {
            int u = tid + i * 256;
            int r = u >> 3, s = u & 7;
            CP_ASYNC16(smem_u32(dA + r * 72 + s * 8),
                       A + (size_t)(row0 + r) * ldA + k0 + s * 8);
            CP_ASYNC16(smem_u32(dB + r * 72 + s * 8),
                       Bt + (size_t)(col0 + r) * ldA + k0 + s * 8);
        }
    };

    const int nC = K / 64;
    stage(0, 0);
    CP_COMMIT();

    for (int c = 0; c < nC; c++) {
        if (c + 1 < nC) {
            stage((c + 1) & 1, (c + 1) * 64);   // prefetch overlaps compute of c
            CP_COMMIT();
            CP_WAIT1();                          // chunk c ready; c+1 in flight
        } else {
            CP_WAIT0();
        }
        __syncthreads();

        __nv_bfloat16 (*sA)[72] = (__nv_bfloat16(*)[72])(smp + (c & 1) * SBUF);
        __nv_bfloat16 (*sB)[72] = (__nv_bfloat16(*)[72])(smp + 2 * SBUF + (c & 1) * SBUF);

#pragma unroll
        for (int ks = 0; ks < 4; ks++) {
            int kk = ks * 16;
            uint32_t af[4][4];
#pragma unroll
            for (int mt = 0; mt < 4; mt++) {
                int mr = wm * 64 + mt * 16 + (lane & 15);
                int mc = kk + ((lane >> 4) << 3);
                LDMATRIX_X4(af[mt][0], af[mt][1], af[mt][2], af[mt][3],
                            smem_u32(&sA[mr][mc]));
            }
            uint32_t bfr[4][2];
#pragma unroll
            for (int np = 0; np < 2; np++) {
                int nr = wn * 32 + np * 16 + (lane & 7) + ((lane >> 4) << 3);
                int nc = kk + (((lane >> 3) & 1) << 3);
                uint32_t r0, r1, r2, r3;
                LDMATRIX_X4(r0, r1, r2, r3, smem_u32(&sB[nr][nc]));
                bfr[np * 2][0] = r0;     bfr[np * 2][1] = r1;
                bfr[np * 2 + 1][0] = r2; bfr[np * 2 + 1][1] = r3;
            }
#pragma unroll
            for (int mt = 0; mt < 4; mt++)
#pragma unroll
                for (int nt = 0; nt < 4; nt++)
                    MMA16816(acc[mt][nt], af[mt], bfr[nt]);
        }
        __syncthreads();
    }

    const int mbase = row0 + wm * 64, nbase = col0 + wn * 32;
#pragma unroll
    for (int mt = 0; mt < 4; mt++) {
#pragma unroll
        for (int half = 0; half < 2; half++) {
            int rr = mbase + mt * 16 + (lane >> 2) + half * 8;
            if (EPI == 0) {
                __nv_bfloat16* o = outH + (size_t)rr * C3;
#pragma unroll
                for (int nt = 0; nt < 4; nt++) {
                    int c = nbase + nt * 8 + ((lane & 3) << 1);
                    if (c < Nreal) {
                        __nv_bfloat162 h;
                        h.x = __float2bfloat16(acc[mt][nt][half * 2]     + bias[c]);
                        h.y = __float2bfloat16(acc[mt][nt][half * 2 + 1] + bias[c + 1]);
                        *(__nv_bfloat162*)(o + c) = h;
                    }
                }
            } else if (EPI == 1 || EPI == 3) {
                int gI = (EPI == 1) ? win2glob(rr) : rr;
                float* o = outF + (size_t)gI * CD;
                const float* rs = resid + (size_t)gI * CD;
#pragma unroll
                for (int nt = 0; nt < 4; nt++) {
                    int c = nbase + nt * 8 + ((lane & 3) << 1);
                    if (c < Nreal) {
                        float2 rv = *(const float2*)(rs + c);
                        float2 ov;
                        ov.x = rv.x + acc[mt][nt][half * 2]     + bias[c];
                        ov.y = rv.y + acc[mt][nt][half * 2 + 1] + bias[c + 1];
                        *(float2*)(o + c) = ov;
                    }
                }
            } else { // EPI == 2
                __nv_bfloat16* o = outH + (size_t)rr * KP2;
#pragma unroll
                for (int nt = 0; nt < 4; nt++) {
                    int c = nbase + nt * 8 + ((lane & 3) << 1);
                    if (c < 720) {
                        int n = c >> 1;
                        float u = acc[mt][nt][half * 2]     + bias[n];
                        float v = acc[mt][nt][half * 2 + 1] + bias2[n];
                        float ge = 0.5f * u * (1.f + erff(u * 0.7071067811865475f));
                        o[n] = __float2bfloat16(ge * v);
                    }
                }
            }
        }
    }
}

// ------------------------- self attention (tensor-core, flash-style) -------
// block = (window, head), 128 thr = 4 warps; warp owns 32 query rows.
// SMEM: Qb[128][40] Kb[128][40] bf16 | Vt[32][136] bf16 | bm[128][132] bf16
#define ASM_QB   0
#define ASM_KB   10240
#define ASM_VT   20480
#define ASM_BM   29184
#define ASM_TOT  62976
__global__ __launch_bounds__(128) void attn_self_mma(const float* __restrict__ mask) {
    extern __shared__ __align__(16) char smc[];
    __nv_bfloat16 (*Qb)[40]  = (__nv_bfloat16(*)[40])(smc + ASM_QB);
    __nv_bfloat16 (*Kb)[40]  = (__nv_bfloat16(*)[40])(smc + ASM_KB);
    __nv_bfloat16 (*Vt)[136] = (__nv_bfloat16(*)[136])(smc + ASM_VT);
    __nv_bfloat16* bm        = (__nv_bfloat16*)(smc + ASM_BM);  // stride 132

    int w = blockIdx.x / NHEAD, h = blockIdx.x % NHEAD;
    int tid = threadIdx.x, lane = tid & 31, wid = tid >> 5;
    const __nv_bfloat16* base = g_qkv_s + (size_t)w * 128 * C3;

    // stage Q, K, V (V transposed)
    for (int idx = tid; idx < 128 * 32; idx += 128) {
        int m = idx >> 5, d = idx & 31;
        __nv_bfloat16 z = __float2bfloat16(0.f);
        Qb[m][d] = (d < HDIM) ? base[(size_t)m * C3 + h * HDIM + d]          : z;
        Kb[m][d] = (d < HDIM) ? base[(size_t)m * C3 + CD + h * HDIM + d]     : z;
        Vt[d][m] = (d < HDIM) ? base[(size_t)m * C3 + 2 * CD + h * HDIM + d] : z;
    }
    // stage bias+mask (coalesced)
    {
        const float* bi = g_bias6 + h * NMASK;
        const float* mk = mask + (size_t)w * NMASK;
        for (int idx = tid; idx < NMASK; idx += 128) {
            int n = idx >> 7, m = idx & 127;
            bm[n * 132 + m] = __float2bfloat16(bi[idx] + mk[idx]);
        }
    }
    __syncthreads();

    // ---- S = Q K^T (accS[mt][nt][4], rows wid*32+mt*16+..) ----
    float accS[2][16][4];
#pragma unroll
    for (int a = 0; a < 2; a++)
#pragma unroll
        for (int t = 0; t < 16; t++)
#pragma unroll
            for (int c = 0; c < 4; c++) accS[a][t][c] = 0.f;

#pragma unroll
    for (int ks = 0; ks < 2; ks++) {
        int kk = ks * 16;
        uint32_t af[2][4];
#pragma unroll
        for (int mt = 0; mt < 2; mt++) {
            int mr = wid * 32 + mt * 16 + (lane & 15);
            int mc = kk + ((lane >> 4) << 3);
            LDMATRIX_X4(af[mt][0], af[mt][1], af[mt][2], af[mt][3],
                        smem_u32(&Qb[mr][mc]));
        }
#pragma unroll
        for (int j = 0; j < 8; j++) {        // key tiles, pairs of n8
            int nr = j * 16 + (lane & 7) + ((lane >> 4) << 3);
            int nc = kk + (((lane >> 3) & 1) << 3);
            uint32_t r0, r1, r2, r3;
            LDMATRIX_X4(r0, r1, r2, r3, smem_u32(&Kb[nr][nc]));
            uint32_t b0[2] = {r0, r1}, b1[2] = {r2, r3};
#pragma unroll
            for (int mt = 0; mt < 2; mt++) {
                MMA16816(accS[mt][2 * j],     af[mt], b0);
                MMA16816(accS[mt][2 * j + 1], af[mt], b1);
            }
        }
    }

    // ---- softmax (register, per lane-quad) + pack P to bf16 frags ----
    uint32_t pf[2][16][2];
    float linv[2][2];
#pragma unroll
    for (int mt = 0; mt < 2; mt++) {
        int row0 = wid * 32 + mt * 16 + (lane >> 2);
        int row1 = row0 + 8;
        float mx0 = -1e30f, mx1 = -1e30f;
#pragma unroll
        for (int t = 0; t < 16; t++) {
            int col = t * 8 + ((lane & 3) << 1);
            uint32_t u0 = *(const uint32_t*)(bm + row0 * 132 + col);
            uint32_t u1 = *(const uint32_t*)(bm + row1 * 132 + col);
            __nv_bfloat162 h0 = *(__nv_bfloat162*)&u0;
            __nv_bfloat162 h1 = *(__nv_bfloat162*)&u1;
            accS[mt][t][0] = accS[mt][t][0] * SCALE_F + __bfloat162float(h0.x);
            accS[mt][t][1] = accS[mt][t][1] * SCALE_F + __bfloat162float(h0.y);
            accS[mt][t][2] = accS[mt][t][2] * SCALE_F + __bfloat162float(h1.x);
            accS[mt][t][3] = accS[mt][t][3] * SCALE_F + __bfloat162float(h1.y);
            mx0 = fmaxf(mx0, fmaxf(accS[mt][t][0], accS[mt][t][1]));
            mx1 = fmaxf(mx1, fmaxf(accS[mt][t][2], accS[mt][t][3]));
        }
        mx0 = fmaxf(mx0, __shfl_xor_sync(0xffffffffu, mx0, 1));
        mx0 = fmaxf(mx0, __shfl_xor_sync(0xffffffffu, mx0, 2));
        mx1 = fmaxf(mx1, __shfl_xor_sync(0xffffffffu, mx1, 1));
        mx1 = fmaxf(mx1, __shfl_xor_sync(0xffffffffu, mx1, 2));
        float l0 = 0.f, l1 = 0.f;
#pragma unroll
        for (int t = 0; t < 16; t++) {
            float p0 = __expf(accS[mt][t][0] - mx0);
            float p1 = __expf(accS[mt][t][1] - mx0);
            float p2 = __expf(accS[mt][t][2] - mx1);
            float p3 = __expf(accS[mt][t][3] - mx1);
            l0 += p0 + p1; l1 += p2 + p3;
            __nv_bfloat162 q0 = __floats2bfloat162_rn(p0, p1);
            __nv_bfloat162 q1 = __floats2bfloat162_rn(p2, p3);
            pf[mt][t][0] = *(uint32_t*)&q0;
            pf[mt][t][1] = *(uint32_t*)&q1;
        }
        l0 += __shfl_xor_sync(0xffffffffu, l0, 1);
        l0 += __shfl_xor_sync(0xffffffffu, l0, 2);
        l1 += __shfl_xor_sync(0xffffffffu, l1, 1);
        l1 += __shfl_xor_sync(0xffffffffu, l1, 2);
        linv[mt][0] = 1.f / l0;
        linv[mt][1] = 1.f / l1;
    }

    // ---- O = P V  (A frags from pf registers, B frags from Vt) ----
    float accO[2][4][4];
#pragma unroll
    for (int a = 0; a < 2; a++)
#pragma unroll
        for (int b = 0; b < 4; b++)
#pragma unroll
            for (int c = 0; c < 4; c++) accO[a][b][c] = 0.f;

#pragma unroll
    for (int ks = 0; ks < 8; ks++) {         // k = token dim, 16 per step
        uint32_t bfr[4][2];
#pragma unroll
        for (int np = 0; np < 2; np++) {
            int nr = np * 16 + (lane & 7) + ((lane >> 4) << 3);
            int nc = ks * 16 + (((lane >> 3) & 1) << 3);
            uint32_t r0, r1, r2, r3;
            LDMATRIX_X4(r0, r1, r2, r3, smem_u32(&Vt[nr][nc]));
            bfr[np * 2][0] = r0;     bfr[np * 2][1] = r1;
            bfr[np * 2 + 1][0] = r2; bfr[np * 2 + 1][1] = r3;
        }
#pragma unroll
        for (int mt = 0; mt < 2; mt++) {
            uint32_t am[4] = {pf[mt][2 * ks][0], pf[mt][2 * ks][1],
                              pf[mt][2 * ks + 1][0], pf[mt][2 * ks + 1][1]};
#pragma unroll
            for (int nt = 0; nt < 4; nt++)
                MMA16816(accO[mt][nt], am, bfr[nt]);
        }
    }

    // ---- write O -> g_xo[:, 180 + h*30 + col] ----
#pragma unroll
    for (int mt = 0; mt < 2; mt++) {
#pragma unroll
        for (int half = 0; half < 2; half++) {
            int row = wid * 32 + mt * 16 + (lane >> 2) + half * 8;
            float inv = linv[mt][half];
            __nv_bfloat16* o = g_xo + (size_t)(w * 128 + row) * KP2 + CD + h * HDIM;
#pragma unroll
            for (int nt = 0; nt < 4; nt++) {
                int col = nt * 8 + ((lane & 3) << 1);
                if (col < HDIM) {
                    __nv_bfloat162 hv;
                    hv.x = __float2bfloat16(accO[mt][nt][half * 2]     * inv);
                    hv.y = __float2bfloat16(accO[mt][nt][half * 2 + 1] * inv);
                    *(__nv_bfloat162*)(o + col) = hv;
                }
            }
        }
    }
}

// ------------------------- mutual attention (scalar) -----------------------
__global__ __launch_bounds__(64) void attn_mut_kernel(const float* __restrict__ mask) {
    __shared__ float ks[64 * 32];
    __shared__ float vs[64 * 32];
    __shared__ float sc[64 * 65];
    int b = blockIdx.x;
    int part = b & 1, h = (b >> 1) % NHEAD, w = b / (2 * NHEAD);
    int t = threadIdx.x;
    const __nv_bfloat16* base = g_qkv_m + (size_t)w * 128 * C3;
    int kvoff = part * 64;
    int qoff  = 64 - kvoff;

    for (int idx = t; idx < 64 * HDIM; idx += 64) {
        int m = idx / HDIM, d = idx - m * HDIM;
        ks[m * 32 + d] = __bfloat162float(base[(size_t)(kvoff + m) * C3 + CD   + h * HDIM + d]);
        vs[m * 32 + d] = __bfloat162float(base[(size_t)(kvoff + m) * C3 + 2*CD + h * HDIM + d]);
    }
    const float* mk = mask + (size_t)w * NMASK;
    for (int idx = t; idx < 64 * 64; idx += 64) {
        int n = idx >> 6, m = idx & 63;
        sc[n * 65 + m] = mk[n * 128 + m];
    }
    __syncthreads();

    float q[HDIM];
#pragma unroll
    for (int d = 0; d < HDIM; d++)
        q[d] = __bfloat162float(base[(size_t)(qoff + t) * C3 + h * HDIM + d]) * SCALE_F;

    float* srow = sc + t * 65;
    float mx = -1e30f;
    for (int m = 0; m < 64; m++) {
        const float* kr = ks + m * 32;
        float s = srow[m];
#pragma unroll
        for (int d4 = 0; d4 < 7; d4++) {
            float4 k4 = *(const float4*)(kr + d4 * 4);
            s += q[d4*4+0]*k4.x + q[d4*4+1]*k4.y + q[d4*4+2]*k4.z + q[d4*4+3]*k4.w;
        }
        s += q[28] * kr[28] + q[29] * kr[29];
        srow[m] = s;
        mx = fmaxf(mx, s);
    }
    float ssum = 0.f;
    for (int m = 0; m < 64; m++) {
        float p = __expf(srow[m] - mx);
        srow[m] = p; ssum += p;
    }
    float o[HDIM] = {};
    for (int m = 0; m < 64; m++) {
        float p = srow[m];
        const float* vr = vs + m * 32;
#pragma unroll
        for (int d4 = 0; d4 < 7; d4++) {
            float4 v4 = *(const float4*)(vr + d4 * 4);
            o[d4*4+0] += p*v4.x; o[d4*4+1] += p*v4.y;
            o[d4*4+2] += p*v4.z; o[d4*4+3] += p*v4.w;
        }
        o[28] += p * vr[28]; o[29] += p * vr[29];
    }
    float inv = 1.f / ssum;
    __nv_bfloat16* out = g_xo + (size_t)(w * 128 + part * 64 + t) * KP2 + h * HDIM;
#pragma unroll
    for (int d = 0; d < HDIM; d++) out[d] = __float2bfloat16(o[d] * inv);
}

// ---------------------------------------------------------------------------
extern "C" void kernel_launch(void* const* d_in, const int* in_sizes, int n_in,
                              void* d_out, int out_size) {
    const float* x          = (const float*)d_in[0];
    const float* mask       = (const float*)d_in[1];
    const float* g1         = (const float*)d_in[2];
    const float* b1         = (const float*)d_in[3];
    const float* g2         = (const float*)d_in[4];
    const float* b2         = (const float*)d_in[5];
    const float* w_qkv_self = (const float*)d_in[6];
    const float* b_qkv_self = (const float*)d_in[7];
    const float* w_qkv_mut  = (const float*)d_in[8];
    const float* b_qkv_mut  = (const float*)d_in[9];
    const float* rpb_table  = (const float*)d_in[10];
    const float* pos_bias   = (const float*)d_in[11];
    const float* w_proj     = (const float*)d_in[12];
    const float* b_proj     = (const float*)d_in[13];
    const float* w_fc11     = (const float*)d_in[14];
    const float* b_fc11     = (const float*)d_in[15];
    const float* w_fc12     = (const float*)d_in[16];
    const float* b_fc12     = (const float*)d_in[17];
    const float* w_fc2      = (const float*)d_in[18];
    const float* b_fc2      = (const float*)d_in[19];
    const int*   rpi        = (const int*)d_in[20];
    float* out = (float*)d_out;

    __nv_bfloat16 *p_a1, *p_a1m, *p_qs, *p_qm, *p_xo, *p_a2, *p_hid;
    __nv_bfloat16 *p_wqs, *p_wqm, *p_wpr, *p_wmix, *p_wf2;
    float *p_x1;
    cudaGetSymbolAddress((void**)&p_a1,  g_a1);
    cudaGetSymbolAddress((void**)&p_a1m, g_a1m);
    cudaGetSymbolAddress((void**)&p_qs,  g_qkv_s);
    cudaGetSymbolAddress((void**)&p_qm,  g_qkv_m);
    cudaGetSymbolAddress((void**)&p_xo,  g_xo);
    cudaGetSymbolAddress((void**)&p_a2,  g_a2);
    cudaGetSymbolAddress((void**)&p_hid, g_hid);
    cudaGetSymbolAddress((void**)&p_x1,  g_x1);
    cudaGetSymbolAddress((void**)&p_wqs, g_wqs);
    cudaGetSymbolAddress((void**)&p_wqm, g_wqm);
    cudaGetSymbolAddress((void**)&p_wpr, g_wpr);
    cudaGetSymbolAddress((void**)&p_wmix,g_wmix);
    cudaGetSymbolAddress((void**)&p_wf2, g_wf2);

    cudaFuncSetAttribute(attn_self_mma,
                         cudaFuncAttributeMaxDynamicSharedMemorySize, ASM_TOT);

    int gemm_smem = 4 * SBUF * 2;   // 73728 B
    cudaFuncSetAttribute(mma_gemm<0>, cudaFuncAttributeMaxDynamicSharedMemorySize, gemm_smem);
    cudaFuncSetAttribute(mma_gemm<1>, cudaFuncAttributeMaxDynamicSharedMemorySize, gemm_smem);
    cudaFuncSetAttribute(mma_gemm<2>, cudaFuncAttributeMaxDynamicSharedMemorySize, gemm_smem);
    cudaFuncSetAttribute(mma_gemm<3>, cudaFuncAttributeMaxDynamicSharedMemorySize, gemm_smem);

    // -- prep (tiny) --
    bias6_kernel<<<(NHEAD * NMASK + 255) / 256, 256>>>(rpb_table, rpi);
    transpose_pad<<<(640 * KP1 + 255) / 256, 256>>>(w_qkv_self, p_wqs, CD, C3, KP1, 640);
    transpose_pad<<<(640 * KP1 + 255) / 256, 256>>>(w_qkv_mut,  p_wqm, CD, C3, KP1, 640);
    transpose_pad<<<(256 * KP2 + 255) / 256, 256>>>(w_proj,     p_wpr, C2, CD, KP2, 256);
    transpose_pad<<<(256 * KP2 + 255) / 256, 256>>>(w_fc2,      p_wf2, C2, CD, KP2, 256);
    mix_fc1<<<(768 * KP1 + 255) / 256, 256>>>(w_fc11, w_fc12);
    pad_xo_kernel<<<(NTOK * 24 + 255) / 256, 256>>>();

    // -- LN1 + roll + window partition --
    ln1_kernel<<<NTOK / 8, 256>>>(x, g1, b1, pos_bias);

    // -- qkv GEMMs --
    mma_gemm<0><<<dim3(5, NTOK / 128), 256, gemm_smem>>>(p_a1,  p_wqs, b_qkv_self, nullptr,
                                              nullptr, p_qs, nullptr, KP1, KP1, C3);
    mma_gemm<0><<<dim3(5, NTOK / 128), 256, gemm_smem>>>(p_a1m, p_wqm, b_qkv_mut, nullptr,
                                              nullptr, p_qm, nullptr, KP1, KP1, C3);
    // -- attention --
    attn_self_mma<<<NWIN * NHEAD, 128, ASM_TOT>>>(mask);
    attn_mut_kernel<<<NWIN * NHEAD * 2, 64>>>(mask);
    // -- proj (+win_rev+roll+resid) --
    mma_gemm<1><<<dim3(2, NTOK / 128), 256, gemm_smem>>>(p_xo, p_wpr, b_proj, nullptr,
                                              p_x1, nullptr, x, KP2, KP2, CD);
    // -- LN2 --
    ln2_kernel<<<NTOK / 8, 256>>>(g2, b2);
    // -- fc1 (fused GEGLU) --
    mma_gemm<2><<<dim3(6, NTOK / 128), 256, gemm_smem>>>(p_a2, p_wmix, b_fc11, b_fc12,
                                              nullptr, p_hid, nullptr, KP1, KP1, 720);
    // -- fc2 + residual --
    mma_gemm<3><<<dim3(2, NTOK / 128), 256, gemm_smem>>>(p_hid, p_wf2, b_fc2, nullptr,
                                              out, nullptr, p_x1, KP2, KP2, CD);
    (void)in_sizes; (void)n_in; (void)out_size;
}

// round 14
// speedup vs baseline: 3.9620x; 1.2506x over previous
#include <cuda_runtime.h>
#include <cuda_bf16.h>
#include <math.h>
#include <stdint.h>

// ---------------------------------------------------------------------------
// B=1, D=6, H=128, W=128, C=180, NH=6, HD=30, WS=(2,8,8) -> N=128/window,
// 768 windows, SS=(1,4,4), HID=360
// ---------------------------------------------------------------------------
#define NTOK   98304
#define CD     180
#define C3     540
#define C2     360
#define NWIN   768
#define NHEAD  6
#define HDIM   30
#define NMASK  16384
#define KP1    192
#define KP2    384
#define SCALE_F 0.18257418583505536f

// ------------------------- scratch (static, no alloc) ----------------------
__device__ __nv_bfloat16 g_a1 [(size_t)NTOK * KP1];
__device__ __nv_bfloat16 g_a1m[(size_t)NTOK * KP1];
__device__ __nv_bfloat16 g_qkv_s[(size_t)NTOK * C3];
__device__ __nv_bfloat16 g_qkv_m[(size_t)NTOK * C3];
__device__ __nv_bfloat16 g_xo  [(size_t)NTOK * KP2];
__device__ float         g_x1  [(size_t)NTOK * CD];
__device__ __nv_bfloat16 g_a2  [(size_t)NTOK * KP1];
__device__ __nv_bfloat16 g_hid [(size_t)NTOK * KP2];
__device__ float         g_bias6[NHEAD * NMASK];
__device__ __nv_bfloat16 g_wqs [640 * KP1];
__device__ __nv_bfloat16 g_wqm [640 * KP1];
__device__ __nv_bfloat16 g_wpr [256 * KP2];
__device__ __nv_bfloat16 g_wmix[768 * KP1];
__device__ __nv_bfloat16 g_wf2 [256 * KP2];

__device__ __forceinline__ int win2glob(int r) {
    int w = r >> 7, n = r & 127;
    int dblk = w >> 8, hblk = (w >> 4) & 15, wblk = w & 15;
    int wd = n >> 6,  wh = (n >> 3) & 7,   ww = n & 7;
    int d = dblk * 2 + wd + 1; if (d >= 6) d -= 6;
    int hh = (hblk * 8 + wh + 4) & 127;
    int w2 = (wblk * 8 + ww + 4) & 127;
    return (d * 128 + hh) * 128 + w2;
}

__device__ __forceinline__ uint32_t smem_u32(const void* p) {
    uint32_t a;
    asm("{ .reg .u64 t; cvta.to.shared.u64 t, %1; cvt.u32.u64 %0, t; }"
        : "=r"(a) : "l"(p));
    return a;
}

#define LDMATRIX_X4(r0, r1, r2, r3, addr) \
    asm volatile("ldmatrix.sync.aligned.m8n8.x4.shared.b16 {%0,%1,%2,%3}, [%4];" \
        : "=r"(r0), "=r"(r1), "=r"(r2), "=r"(r3) : "r"(addr))

#define MMA16816(d, a, b) \
    asm volatile("mma.sync.aligned.m16n8k16.row.col.f32.bf16.bf16.f32 " \
        "{%0,%1,%2,%3}, {%4,%5,%6,%7}, {%8,%9}, {%0,%1,%2,%3};" \
        : "+f"((d)[0]), "+f"((d)[1]), "+f"((d)[2]), "+f"((d)[3]) \
        : "r"((a)[0]), "r"((a)[1]), "r"((a)[2]), "r"((a)[3]), \
          "r"((b)[0]), "r"((b)[1]))

#define CP_ASYNC16(dst, src) \
    asm volatile("cp.async.cg.shared.global [%0], [%1], 16;" :: "r"(dst), "l"(src))
#define CP_COMMIT() asm volatile("cp.async.commit_group;")
#define CP_WAIT0()  asm volatile("cp.async.wait_group 0;")
#define CP_WAIT1()  asm volatile("cp.async.wait_group 1;")
#define CP_WAIT2()  asm volatile("cp.async.wait_group 2;")

// ------------------------- prep kernels ------------------------------------
__global__ void bias6_kernel(const float* __restrict__ rpb, const int* __restrict__ rpi) {
    int t = blockIdx.x * 256 + threadIdx.x;
    if (t < NHEAD * NMASK) {
        int h = t >> 14, nm = t & (NMASK - 1);
        g_bias6[t] = rpb[rpi[nm] * NHEAD + h];
    }
}

__global__ void transpose_pad(const float* __restrict__ src, __nv_bfloat16* __restrict__ dst,
                              int K, int N, int Kpad, int Nrows) {
    int idx = blockIdx.x * 256 + threadIdx.x;
    if (idx >= Nrows * Kpad) return;
    int n = idx / Kpad, k = idx - n * Kpad;
    float v = (n < N && k < K) ? src[(size_t)k * N + n] : 0.f;
    dst[idx] = __float2bfloat16(v);
}

__global__ void mix_fc1(const float* __restrict__ w11, const float* __restrict__ w12) {
    int idx = blockIdx.x * 256 + threadIdx.x;
    if (idx >= 768 * KP1) return;
    int r = idx / KP1, k = idx - r * KP1;
    int n = r >> 1;
    float v = 0.f;
    if (k < CD && n < C2)
        v = (r & 1) ? w12[(size_t)k * C2 + n] : w11[(size_t)k * C2 + n];
    g_wmix[idx] = __float2bfloat16(v);
}

__global__ void pad_xo_kernel() {
    int idx = blockIdx.x * 256 + threadIdx.x;
    if (idx < NTOK * 24) {
        int r = idx / 24, c = 360 + idx % 24;
        g_xo [(size_t)r * KP2 + c] = __float2bfloat16(0.f);
        g_hid[(size_t)r * KP2 + c] = __float2bfloat16(0.f);
    }
}

// ------------------------- LayerNorms (warp/token, bf16 out) ---------------
__global__ void ln1_kernel(const float* __restrict__ x, const float* __restrict__ g,
                           const float* __restrict__ b, const float* __restrict__ pb) {
    int r = blockIdx.x * 8 + (threadIdx.x >> 5);
    int lane = threadIdx.x & 31;
    const float* xr = x + (size_t)win2glob(r) * CD;
    float vals[6], s = 0.f, s2 = 0.f;
#pragma unroll
    for (int i = 0; i < 6; i++) {
        int c = lane + i * 32;
        float v = (c < CD) ? xr[c] : 0.f;
        vals[i] = v; s += v; s2 += v * v;
    }
#pragma unroll
    for (int o = 16; o; o >>= 1) {
        s  += __shfl_xor_sync(0xffffffffu, s,  o);
        s2 += __shfl_xor_sync(0xffffffffu, s2, o);
    }
    float m = s * (1.f / CD);
    float rstd = rsqrtf(s2 * (1.f / CD) - m * m + 1e-5f);
    __nv_bfloat16* y1 = g_a1  + (size_t)r * KP1;
    __nv_bfloat16* y2 = g_a1m + (size_t)r * KP1;
    const float* pbr = pb + (size_t)(r & 63) * CD;
#pragma unroll
    for (int i = 0; i < 6; i++) {
        int c = lane + i * 32;
        if (c < CD) {
            float v = (vals[i] - m) * rstd * g[c] + b[c];
            y1[c] = __float2bfloat16(v);
            y2[c] = __float2bfloat16(v + pbr[c]);
        } else {
            y1[c] = __float2bfloat16(0.f);
            y2[c] = __float2bfloat16(0.f);
        }
    }
}

__global__ void ln2_kernel(const float* __restrict__ g, const float* __restrict__ b) {
    int r = blockIdx.x * 8 + (threadIdx.x >> 5);
    int lane = threadIdx.x & 31;
    const float* xr = g_x1 + (size_t)r * CD;
    float vals[6], s = 0.f, s2 = 0.f;
#pragma unroll
    for (int i = 0; i < 6; i++) {
        int c = lane + i * 32;
        float v = (c < CD) ? xr[c] : 0.f;
        vals[i] = v; s += v; s2 += v * v;
    }
#pragma unroll
    for (int o = 16; o; o >>= 1) {
        s  += __shfl_xor_sync(0xffffffffu, s,  o);
        s2 += __shfl_xor_sync(0xffffffffu, s2, o);
    }
    float m = s * (1.f / CD);
    float rstd = rsqrtf(s2 * (1.f / CD) - m * m + 1e-5f);
    __nv_bfloat16* y = g_a2 + (size_t)r * KP1;
#pragma unroll
    for (int i = 0; i < 6; i++) {
        int c = lane + i * 32;
        float v = (c < CD) ? (vals[i] - m) * rstd * g[c] + b[c] : 0.f;
        y[c] = __float2bfloat16(v);
    }
}

// ------------------------- mma.sync bf16 GEMM (3-stage cp.async ring) ------
#define SBUF 9216   // halves per buffer (128*72)
template<int EPI>
__global__ __launch_bounds__(256) void mma_gemm(
    const __nv_bfloat16* __restrict__ A, const __nv_bfloat16* __restrict__ Bt,
    const float* __restrict__ bias, const float* __restrict__ bias2,
    float* __restrict__ outF, __nv_bfloat16* __restrict__ outH,
    const float* __restrict__ resid,
    int ldA, int K, int Nreal)
{
    extern __shared__ __align__(16) __nv_bfloat16 smp[];
    const int tid = threadIdx.x, lane = tid & 31, wid = tid >> 5;
    const int wm = wid >> 2, wn = wid & 3;
    const int row0 = blockIdx.y * 128, col0 = blockIdx.x * 128;

    float acc[4][4][4];
#pragma unroll
    for (int a = 0; a < 4; a++)
#pragma unroll
        for (int b = 0; b < 4; b++)
#pragma unroll
            for (int c = 0; c < 4; c++) acc[a][b][c] = 0.f;

    // layout: A bufs [0..3*SBUF), B bufs [3*SBUF..6*SBUF)
    auto stage = [&](int buf, int k0) {
        __nv_bfloat16* dA = smp + buf * SBUF;
        __nv_bfloat16* dB = smp + 3 * SBUF + buf * SBUF;
#pragma unroll
        for (int i = 0; i < 4; i++) {
            int u = tid + i * 256;
            int r = u >> 3, s = u & 7;
            CP_ASYNC16(smem_u32(dA + r * 72 + s * 8),
                       A + (size_t)(row0 + r) * ldA + k0 + s * 8);
            CP_ASYNC16(smem_u32(dB + r * 72 + s * 8),
                       Bt + (size_t)(col0 + r) * ldA + k0 + s * 8);
        }
    };

    const int nC = K / 64;
    const int nst = (nC < 3) ? nC : 3;
    for (int i = 0; i < nst; i++) { stage(i, i * 64); CP_COMMIT(); }

    for (int c = 0; c < nC; c++) {
        int wg = nC - 1 - c; if (wg > 2) wg = 2;
        if (wg == 2) CP_WAIT2(); else if (wg == 1) CP_WAIT1(); else CP_WAIT0();
        __syncthreads();

        int buf = c % 3;
        __nv_bfloat16 (*sA)[72] = (__nv_bfloat16(*)[72])(smp + buf * SBUF);
        __nv_bfloat16 (*sB)[72] = (__nv_bfloat16(*)[72])(smp + 3 * SBUF + buf * SBUF);

#pragma unroll
        for (int ks = 0; ks < 4; ks++) {
            int kk = ks * 16;
            uint32_t af[4][4];
#pragma unroll
            for (int mt = 0; mt < 4; mt++) {
                int mr = wm * 64 + mt * 16 + (lane & 15);
                int mc = kk + ((lane >> 4) << 3);
                LDMATRIX_X4(af[mt][0], af[mt][1], af[mt][2], af[mt][3],
                            smem_u32(&sA[mr][mc]));
            }
            uint32_t bfr[4][2];
#pragma unroll
            for (int np = 0; np < 2; np++) {
                int nr = wn * 32 + np * 16 + (lane & 7) + ((lane >> 4) << 3);
                int nc = kk + (((lane >> 3) & 1) << 3);
                uint32_t r0, r1, r2, r3;
                LDMATRIX_X4(r0, r1, r2, r3, smem_u32(&sB[nr][nc]));
                bfr[np * 2][0] = r0;     bfr[np * 2][1] = r1;
                bfr[np * 2 + 1][0] = r2; bfr[np * 2 + 1][1] = r3;
            }
#pragma unroll
            for (int mt = 0; mt < 4; mt++)
#pragma unroll
                for (int nt = 0; nt < 4; nt++)
                    MMA16816(acc[mt][nt], af[mt], bfr[nt]);
        }
        __syncthreads();
        if (c + 3 < nC) { stage((c + 3) % 3, (c + 3) * 64); CP_COMMIT(); }
    }

    const int mbase = row0 + wm * 64, nbase = col0 + wn * 32;
#pragma unroll
    for (int mt = 0; mt < 4; mt++) {
#pragma unroll
        for (int half = 0; half < 2; half++) {
            int rr = mbase + mt * 16 + (lane >> 2) + half * 8;
            if (EPI == 0) {
                __nv_bfloat16* o = outH + (size_t)rr * C3;
#pragma unroll
                for (int nt = 0; nt < 4; nt++) {
                    int c = nbase + nt * 8 + ((lane & 3) << 1);
                    if (c < Nreal) {
                        __nv_bfloat162 h;
                        h.x = __float2bfloat16(acc[mt][nt][half * 2]     + bias[c]);
                        h.y = __float2bfloat16(acc[mt][nt][half * 2 + 1] + bias[c + 1]);
                        *(__nv_bfloat162*)(o + c) = h;
                    }
                }
            } else if (EPI == 1 || EPI == 3) {
                int gI = (EPI == 1) ? win2glob(rr) : rr;
                float* o = outF + (size_t)gI * CD;
                const float* rs = resid + (size_t)gI * CD;
#pragma unroll
                for (int nt = 0; nt < 4; nt++) {
                    int c = nbase + nt * 8 + ((lane & 3) << 1);
                    if (c < Nreal) {
                        float2 rv = *(const float2*)(rs + c);
                        float2 ov;
                        ov.x = rv.x + acc[mt][nt][half * 2]     + bias[c];
                        ov.y = rv.y + acc[mt][nt][half * 2 + 1] + bias[c + 1];
                        *(float2*)(o + c) = ov;
                    }
                }
            } else { // EPI == 2
                __nv_bfloat16* o = outH + (size_t)rr * KP2;
#pragma unroll
                for (int nt = 0; nt < 4; nt++) {
                    int c = nbase + nt * 8 + ((lane & 3) << 1);
                    if (c < 720) {
                        int n = c >> 1;
                        float u = acc[mt][nt][half * 2]     + bias[n];
                        float v = acc[mt][nt][half * 2 + 1] + bias2[n];
                        float ge = 0.5f * u * (1.f + erff(u * 0.7071067811865475f));
                        o[n] = __float2bfloat16(ge * v);
                    }
                }
            }
        }
    }
}

// ------------------------- self attention (tensor-core) --------------------
#define ASM_QB   0
#define ASM_KB   10240
#define ASM_VT   20480
#define ASM_BM   29184
#define ASM_TOT  62976
__global__ __launch_bounds__(128) void attn_self_mma(const float* __restrict__ mask) {
    extern __shared__ __align__(16) char smc[];
    __nv_bfloat16 (*Qb)[40]  = (__nv_bfloat16(*)[40])(smc + ASM_QB);
    __nv_bfloat16 (*Kb)[40]  = (__nv_bfloat16(*)[40])(smc + ASM_KB);
    __nv_bfloat16 (*Vt)[136] = (__nv_bfloat16(*)[136])(smc + ASM_VT);
    __nv_bfloat16* bm        = (__nv_bfloat16*)(smc + ASM_BM);  // stride 132

    int w = blockIdx.x / NHEAD, h = blockIdx.x % NHEAD;
    int tid = threadIdx.x, lane = tid & 31, wid = tid >> 5;
    const __nv_bfloat16* base = g_qkv_s + (size_t)w * 128 * C3;

    for (int idx = tid; idx < 128 * 32; idx += 128) {
        int m = idx >> 5, d = idx & 31;
        __nv_bfloat16 z = __float2bfloat16(0.f);
        Qb[m][d] = (d < HDIM) ? base[(size_t)m * C3 + h * HDIM + d]          : z;
        Kb[m][d] = (d < HDIM) ? base[(size_t)m * C3 + CD + h * HDIM + d]     : z;
        Vt[d][m] = (d < HDIM) ? base[(size_t)m * C3 + 2 * CD + h * HDIM + d] : z;
    }
    {
        const float* bi = g_bias6 + h * NMASK;
        const float* mk = mask + (size_t)w * NMASK;
        for (int idx = tid; idx < NMASK; idx += 128) {
            int n = idx >> 7, m = idx & 127;
            bm[n * 132 + m] = __float2bfloat16(bi[idx] + mk[idx]);
        }
    }
    __syncthreads();

    float accS[2][16][4];
#pragma unroll
    for (int a = 0; a < 2; a++)
#pragma unroll
        for (int t = 0; t < 16; t++)
#pragma unroll
            for (int c = 0; c < 4; c++) accS[a][t][c] = 0.f;

#pragma unroll
    for (int ks = 0; ks < 2; ks++) {
        int kk = ks * 16;
        uint32_t af[2][4];
#pragma unroll
        for (int mt = 0; mt < 2; mt++) {
            int mr = wid * 32 + mt * 16 + (lane & 15);
            int mc = kk + ((lane >> 4) << 3);
            LDMATRIX_X4(af[mt][0], af[mt][1], af[mt][2], af[mt][3],
                        smem_u32(&Qb[mr][mc]));
        }
#pragma unroll
        for (int j = 0; j < 8; j++) {
            int nr = j * 16 + (lane & 7) + ((lane >> 4) << 3);
            int nc = kk + (((lane >> 3) & 1) << 3);
            uint32_t r0, r1, r2, r3;
            LDMATRIX_X4(r0, r1, r2, r3, smem_u32(&Kb[nr][nc]));
            uint32_t b0[2] = {r0, r1}, b1[2] = {r2, r3};
#pragma unroll
            for (int mt = 0; mt < 2; mt++) {
                MMA16816(accS[mt][2 * j],     af[mt], b0);
                MMA16816(accS[mt][2 * j + 1], af[mt], b1);
            }
        }
    }

    uint32_t pf[2][16][2];
    float linv[2][2];
#pragma unroll
    for (int mt = 0; mt < 2; mt++) {
        int row0 = wid * 32 + mt * 16 + (lane >> 2);
        int row1 = row0 + 8;
        float mx0 = -1e30f, mx1 = -1e30f;
#pragma unroll
        for (int t = 0; t < 16; t++) {
            int col = t * 8 + ((lane & 3) << 1);
            uint32_t u0 = *(const uint32_t*)(bm + row0 * 132 + col);
            uint32_t u1 = *(const uint32_t*)(bm + row1 * 132 + col);
            __nv_bfloat162 h0 = *(__nv_bfloat162*)&u0;
            __nv_bfloat162 h1 = *(__nv_bfloat162*)&u1;
            accS[mt][t][0] = accS[mt][t][0] * SCALE_F + __bfloat162float(h0.x);
            accS[mt][t][1] = accS[mt][t][1] * SCALE_F + __bfloat162float(h0.y);
            accS[mt][t][2] = accS[mt][t][2] * SCALE_F + __bfloat162float(h1.x);
            accS[mt][t][3] = accS[mt][t][3] * SCALE_F + __bfloat162float(h1.y);
            mx0 = fmaxf(mx0, fmaxf(accS[mt][t][0], accS[mt][t][1]));
            mx1 = fmaxf(mx1, fmaxf(accS[mt][t][2], accS[mt][t][3]));
        }
        mx0 = fmaxf(mx0, __shfl_xor_sync(0xffffffffu, mx0, 1));
        mx0 = fmaxf(mx0, __shfl_xor_sync(0xffffffffu, mx0, 2));
        mx1 = fmaxf(mx1, __shfl_xor_sync(0xffffffffu, mx1, 1));
        mx1 = fmaxf(mx1, __shfl_xor_sync(0xffffffffu, mx1, 2));
        float l0 = 0.f, l1 = 0.f;
#pragma unroll
        for (int t = 0; t < 16; t++) {
            float p0 = __expf(accS[mt][t][0] - mx0);
            float p1 = __expf(accS[mt][t][1] - mx0);
            float p2 = __expf(accS[mt][t][2] - mx1);
            float p3 = __expf(accS[mt][t][3] - mx1);
            l0 += p0 + p1; l1 += p2 + p3;
            __nv_bfloat162 q0 = __floats2bfloat162_rn(p0, p1);
            __nv_bfloat162 q1 = __floats2bfloat162_rn(p2, p3);
            pf[mt][t][0] = *(uint32_t*)&q0;
            pf[mt][t][1] = *(uint32_t*)&q1;
        }
        l0 += __shfl_xor_sync(0xffffffffu, l0, 1);
        l0 += __shfl_xor_sync(0xffffffffu, l0, 2);
        l1 += __shfl_xor_sync(0xffffffffu, l1, 1);
        l1 += __shfl_xor_sync(0xffffffffu, l1, 2);
        linv[mt][0] = 1.f / l0;
        linv[mt][1] = 1.f / l1;
    }

    float accO[2][4][4];
#pragma unroll
    for (int a = 0; a < 2; a++)
#pragma unroll
        for (int b = 0; b < 4; b++)
#pragma unroll
            for (int c = 0; c < 4; c++) accO[a][b][c] = 0.f;

#pragma unroll
    for (int ks = 0; ks < 8; ks++) {
        uint32_t bfr[4][2];
#pragma unroll
        for (int np = 0; np < 2; np++) {
            int nr = np * 16 + (lane & 7) + ((lane >> 4) << 3);
            int nc = ks * 16 + (((lane >> 3) & 1) << 3);
            uint32_t r0, r1, r2, r3;
            LDMATRIX_X4(r0, r1, r2, r3, smem_u32(&Vt[nr][nc]));
            bfr[np * 2][0] = r0;     bfr[np * 2][1] = r1;
            bfr[np * 2 + 1][0] = r2; bfr[np * 2 + 1][1] = r3;
        }
#pragma unroll
        for (int mt = 0; mt < 2; mt++) {
            uint32_t am[4] = {pf[mt][2 * ks][0], pf[mt][2 * ks][1],
                              pf[mt][2 * ks + 1][0], pf[mt][2 * ks + 1][1]};
#pragma unroll
            for (int nt = 0; nt < 4; nt++)
                MMA16816(accO[mt][nt], am, bfr[nt]);
        }
    }

#pragma unroll
    for (int mt = 0; mt < 2; mt++) {
#pragma unroll
        for (int half = 0; half < 2; half++) {
            int row = wid * 32 + mt * 16 + (lane >> 2) + half * 8;
            float inv = linv[mt][half];
            __nv_bfloat16* o = g_xo + (size_t)(w * 128 + row) * KP2 + CD + h * HDIM;
#pragma unroll
            for (int nt = 0; nt < 4; nt++) {
                int col = nt * 8 + ((lane & 3) << 1);
                if (col < HDIM) {
                    __nv_bfloat162 hv;
                    hv.x = __float2bfloat16(accO[mt][nt][half * 2]     * inv);
                    hv.y = __float2bfloat16(accO[mt][nt][half * 2 + 1] * inv);
                    *(__nv_bfloat162*)(o + col) = hv;
                }
            }
        }
    }
}

// ------------------------- mutual attention (tensor-core) ------------------
// block = (window, head, part), 64 thr = 2 warps; warp owns 32 query rows.
// part 0: q rows 64..127, kv 0..63 -> out rows 0..63
// part 1: q rows 0..63,  kv 64..127 -> out rows 64..127
__global__ __launch_bounds__(64) void attn_mut_mma(const float* __restrict__ mask) {
    __shared__ __align__(16) __nv_bfloat16 Qb[64][40];
    __shared__ __align__(16) __nv_bfloat16 Kb[64][40];
    __shared__ __align__(16) __nv_bfloat16 Vt[32][72];
    __shared__ __align__(16) __nv_bfloat16 bm[64 * 68];

    int b = blockIdx.x;
    int part = b & 1, h = (b >> 1) % NHEAD, w = b / (2 * NHEAD);
    int tid = threadIdx.x, lane = tid & 31, wid = tid >> 5;
    const __nv_bfloat16* base = g_qkv_m + (size_t)w * 128 * C3;
    int kvoff = part * 64;
    int qoff  = 64 - kvoff;

    for (int idx = tid; idx < 64 * 32; idx += 64) {
        int m = idx >> 5, d = idx & 31;
        __nv_bfloat16 z = __float2bfloat16(0.f);
        Qb[m][d] = (d < HDIM) ? base[(size_t)(qoff + m) * C3 + h * HDIM + d]           : z;
        Kb[m][d] = (d < HDIM) ? base[(size_t)(kvoff + m) * C3 + CD + h * HDIM + d]     : z;
        Vt[d][m] = (d < HDIM) ? base[(size_t)(kvoff + m) * C3 + 2 * CD + h * HDIM + d] : z;
    }
    {
        const float* mk = mask + (size_t)w * NMASK;   // top-left 64x64 block
        for (int idx = tid; idx < 64 * 64; idx += 64) {
            int n = idx >> 6, m = idx & 63;
            bm[n * 68 + m] = __float2bfloat16(mk[n * 128 + m]);
        }
    }
    __syncthreads();

    // S = Q K^T : 8 n-tiles of 8 cols
    float accS[2][8][4];
#pragma unroll
    for (int a = 0; a < 2; a++)
#pragma unroll
        for (int t = 0; t < 8; t++)
#pragma unroll
            for (int c = 0; c < 4; c++) accS[a][t][c] = 0.f;

#pragma unroll
    for (int ks = 0; ks < 2; ks++) {
        int kk = ks * 16;
        uint32_t af[2][4];
#pragma unroll
        for (int mt = 0; mt < 2; mt++) {
            int mr = wid * 32 + mt * 16 + (lane & 15);
            int mc = kk + ((lane >> 4) << 3);
            LDMATRIX_X4(af[mt][0], af[mt][1], af[mt][2], af[mt][3],
                        smem_u32(&Qb[mr][mc]));
        }
#pragma unroll
        for (int j = 0; j < 4; j++) {
            int nr = j * 16 + (lane & 7) + ((lane >> 4) << 3);
            int nc = kk + (((lane >> 3) & 1) << 3);
            uint32_t r0, r1, r2, r3;
            LDMATRIX_X4(r0, r1, r2, r3, smem_u32(&Kb[nr][nc]));
            uint32_t b0[2] = {r0, r1}, b1[2] = {r2, r3};
#pragma unroll
            for (int mt = 0; mt < 2; mt++) {
                MMA16816(accS[mt][2 * j],     af[mt], b0);
                MMA16816(accS[mt][2 * j + 1], af[mt], b1);
            }
        }
    }

    // softmax + pack P
    uint32_t pf[2][8][2];
    float linv[2][2];
#pragma unroll
    for (int mt = 0; mt < 2; mt++) {
        int row0 = wid * 32 + mt * 16 + (lane >> 2);
        int row1 = row0 + 8;
        float mx0 = -1e30f, mx1 = -1e30f;
#pragma unroll
        for (int t = 0; t < 8; t++) {
            int col = t * 8 + ((lane & 3) << 1);
            uint32_t u0 = *(const uint32_t*)(bm + row0 * 68 + col);
            uint32_t u1 = *(const uint32_t*)(bm + row1 * 68 + col);
            __nv_bfloat162 h0 = *(__nv_bfloat162*)&u0;
            __nv_bfloat162 h1 = *(__nv_bfloat162*)&u1;
            accS[mt][t][0] = accS[mt][t][0] * SCALE_F + __bfloat162float(h0.x);
            accS[mt][t][1] = accS[mt][t][1] * SCALE_F + __bfloat162float(h0.y);
            accS[mt][t][2] = accS[mt][t][2] * SCALE_F + __bfloat162float(h1.x);
            accS[mt][t][3] = accS[mt][t][3] * SCALE_F + __bfloat162float(h1.y);
            mx0 = fmaxf(mx0, fmaxf(accS[mt][t][0], accS[mt][t][1]));
            mx1 = fmaxf(mx1, fmaxf(accS[mt][t][2], accS[mt][t][3]));
        }
        mx0 = fmaxf(mx0, __shfl_xor_sync(0xffffffffu, mx0, 1));
        mx0 = fmaxf(mx0, __shfl_xor_sync(0xffffffffu, mx0, 2));
        mx1 = fmaxf(mx1, __shfl_xor_sync(0xffffffffu, mx1, 1));
        mx1 = fmaxf(mx1, __shfl_xor_sync(0xffffffffu, mx1, 2));
        float l0 = 0.f, l1 = 0.f;
#pragma unroll
        for (int t = 0; t < 8; t++) {
            float p0 = __expf(accS[mt][t][0] - mx0);
            float p1 = __expf(accS[mt][t][1] - mx0);
            float p2 = __expf(accS[mt][t][2] - mx1);
            float p3 = __expf(accS[mt][t][3] - mx1);
            l0 += p0 + p1; l1 += p2 + p3;
            __nv_bfloat162 q0 = __floats2bfloat162_rn(p0, p1);
            __nv_bfloat162 q1 = __floats2bfloat162_rn(p2, p3);
            pf[mt][t][0] = *(uint32_t*)&q0;
            pf[mt][t][1] = *(uint32_t*)&q1;
        }
        l0 += __shfl_xor_sync(0xffffffffu, l0, 1);
        l0 += __shfl_xor_sync(0xffffffffu, l0, 2);
        l1 += __shfl_xor_sync(0xffffffffu, l1, 1);
        l1 += __shfl_xor_sync(0xffffffffu, l1, 2);
        linv[mt][0] = 1.f / l0;
        linv[mt][1] = 1.f / l1;
    }

    // O = P V (64 tokens -> 4 ks steps)
    float accO[2][4][4];
#pragma unroll
    for (int a = 0; a < 2; a++)
#pragma unroll
        for (int b2_ = 0; b2_ < 4; b2_++)
#pragma unroll
            for (int c = 0; c < 4; c++) accO[a][b2_][c] = 0.f;

#pragma unroll
    for (int ks = 0; ks < 4; ks++) {
        uint32_t bfr[4][2];
#pragma unroll
        for (int np = 0; np < 2; np++) {
            int nr = np * 16 + (lane & 7) + ((lane >> 4) << 3);
            int nc = ks * 16 + (((lane >> 3) & 1) << 3);
            uint32_t r0, r1, r2, r3;
            LDMATRIX_X4(r0, r1, r2, r3, smem_u32(&Vt[nr][nc]));
            bfr[np * 2][0] = r0;     bfr[np * 2][1] = r1;
            bfr[np * 2 + 1][0] = r2; bfr[np * 2 + 1][1] = r3;
        }
#pragma unroll
        for (int mt = 0; mt < 2; mt++) {
            uint32_t am[4] = {pf[mt][2 * ks][0], pf[mt][2 * ks][1],
                              pf[mt][2 * ks + 1][0], pf[mt][2 * ks + 1][1]};
#pragma unroll
            for (int nt = 0; nt < 4; nt++)
                MMA16816(accO[mt][nt], am, bfr[nt]);
        }
    }

    // write O -> g_xo rows part*64 + row, cols h*30 + col
#pragma unroll
    for (int mt = 0; mt < 2; mt++) {
#pragma unroll
        for (int half = 0; half < 2; half++) {
            int row = wid * 32 + mt * 16 + (lane >> 2) + half * 8;
            float inv = linv[mt][half];
            __nv_bfloat16* o = g_xo + (size_t)(w * 128 + part * 64 + row) * KP2 + h * HDIM;
#pragma unroll
            for (int nt = 0; nt < 4; nt++) {
                int col = nt * 8 + ((lane & 3) << 1);
                if (col < HDIM) {
                    __nv_bfloat162 hv;
                    hv.x = __float2bfloat16(accO[mt][nt][half * 2]     * inv);
                    hv.y = __float2bfloat16(accO[mt][nt][half * 2 + 1] * inv);
                    *(__nv_bfloat162*)(o + col) = hv;
                }
            }
        }
    }
}

// ---------------------------------------------------------------------------
extern "C" void kernel_launch(void* const* d_in, const int* in_sizes, int n_in,
                              void* d_out, int out_size) {
    const float* x          = (const float*)d_in[0];
    const float* mask       = (const float*)d_in[1];
    const float* g1         = (const float*)d_in[2];
    const float* b1         = (const float*)d_in[3];
    const float* g2         = (const float*)d_in[4];
    const float* b2         = (const float*)d_in[5];
    const float* w_qkv_self = (const float*)d_in[6];
    const float* b_qkv_self = (const float*)d_in[7];
    const float* w_qkv_mut  = (const float*)d_in[8];
    const float* b_qkv_mut  = (const float*)d_in[9];
    const float* rpb_table  = (const float*)d_in[10];
    const float* pos_bias   = (const float*)d_in[11];
    const float* w_proj     = (const float*)d_in[12];
    const float* b_proj     = (const float*)d_in[13];
    const float* w_fc11     = (const float*)d_in[14];
    const float* b_fc11     = (const float*)d_in[15];
    const float* w_fc12     = (const float*)d_in[16];
    const float* b_fc12     = (const float*)d_in[17];
    const float* w_fc2      = (const float*)d_in[18];
    const float* b_fc2      = (const float*)d_in[19];
    const int*   rpi        = (const int*)d_in[20];
    float* out = (float*)d_out;

    __nv_bfloat16 *p_a1, *p_a1m, *p_qs, *p_qm, *p_xo, *p_a2, *p_hid;
    __nv_bfloat16 *p_wqs, *p_wqm, *p_wpr, *p_wmix, *p_wf2;
    float *p_x1;
    cudaGetSymbolAddress((void**)&p_a1,  g_a1);
    cudaGetSymbolAddress((void**)&p_a1m, g_a1m);
    cudaGetSymbolAddress((void**)&p_qs,  g_qkv_s);
    cudaGetSymbolAddress((void**)&p_qm,  g_qkv_m);
    cudaGetSymbolAddress((void**)&p_xo,  g_xo);
    cudaGetSymbolAddress((void**)&p_a2,  g_a2);
    cudaGetSymbolAddress((void**)&p_hid, g_hid);
    cudaGetSymbolAddress((void**)&p_x1,  g_x1);
    cudaGetSymbolAddress((void**)&p_wqs, g_wqs);
    cudaGetSymbolAddress((void**)&p_wqm, g_wqm);
    cudaGetSymbolAddress((void**)&p_wpr, g_wpr);
    cudaGetSymbolAddress((void**)&p_wmix,g_wmix);
    cudaGetSymbolAddress((void**)&p_wf2, g_wf2);

    cudaFuncSetAttribute(attn_self_mma,
                         cudaFuncAttributeMaxDynamicSharedMemorySize, ASM_TOT);

    int gemm_smem = 6 * SBUF * 2;   // 110592 B (A[3] + B[3])
    cudaFuncSetAttribute(mma_gemm<0>, cudaFuncAttributeMaxDynamicSharedMemorySize, gemm_smem);
    cudaFuncSetAttribute(mma_gemm<1>, cudaFuncAttributeMaxDynamicSharedMemorySize, gemm_smem);
    cudaFuncSetAttribute(mma_gemm<2>, cudaFuncAttributeMaxDynamicSharedMemorySize, gemm_smem);
    cudaFuncSetAttribute(mma_gemm<3>, cudaFuncAttributeMaxDynamicSharedMemorySize, gemm_smem);

    // -- prep (tiny) --
    bias6_kernel<<<(NHEAD * NMASK + 255) / 256, 256>>>(rpb_table, rpi);
    transpose_pad<<<(640 * KP1 + 255) / 256, 256>>>(w_qkv_self, p_wqs, CD, C3, KP1, 640);
    transpose_pad<<<(640 * KP1 + 255) / 256, 256>>>(w_qkv_mut,  p_wqm, CD, C3, KP1, 640);
    transpose_pad<<<(256 * KP2 + 255) / 256, 256>>>(w_proj,     p_wpr, C2, CD, KP2, 256);
    transpose_pad<<<(256 * KP2 + 255) / 256, 256>>>(w_fc2,      p_wf2, C2, CD, KP2, 256);
    mix_fc1<<<(768 * KP1 + 255) / 256, 256>>>(w_fc11, w_fc12);
    pad_xo_kernel<<<(NTOK * 24 + 255) / 256, 256>>>();

    // -- LN1 + roll + window partition --
    ln1_kernel<<<NTOK / 8, 256>>>(x, g1, b1, pos_bias);

    // -- qkv GEMMs --
    mma_gemm<0><<<dim3(5, NTOK / 128), 256, gemm_smem>>>(p_a1,  p_wqs, b_qkv_self, nullptr,
                                              nullptr, p_qs, nullptr, KP1, KP1, C3);
    mma_gemm<0><<<dim3(5, NTOK / 128), 256, gemm_smem>>>(p_a1m, p_wqm, b_qkv_mut, nullptr,
                                              nullptr, p_qm, nullptr, KP1, KP1, C3);
    // -- attention (both tensor-core) --
    attn_self_mma<<<NWIN * NHEAD, 128, ASM_TOT>>>(mask);
    attn_mut_mma<<<NWIN * NHEAD * 2, 64>>>(mask);
    // -- proj (+win_rev+roll+resid) --
    mma_gemm<1><<<dim3(2, NTOK / 128), 256, gemm_smem>>>(p_xo, p_wpr, b_proj, nullptr,
                                              p_x1, nullptr, x, KP2, KP2, CD);
    // -- LN2 --
    ln2_kernel<<<NTOK / 8, 256>>>(g2, b2);
    // -- fc1 (fused GEGLU) --
    mma_gemm<2><<<dim3(6, NTOK / 128), 256, gemm_smem>>>(p_a2, p_wmix, b_fc11, b_fc12,
                                              nullptr, p_hid, nullptr, KP1, KP1, 720);
    // -- fc2 + residual --
    mma_gemm<3><<<dim3(2, NTOK / 128), 256, gemm_smem>>>(p_hid, p_wf2, b_fc2, nullptr,
                                              out, nullptr, p_x1, KP2, KP2, CD);
    (void)in_sizes; (void)n_in; (void)out_size;
}

// round 15
// speedup vs baseline: 4.5577x; 1.1504x over previous
#include <cuda_runtime.h>
#include <cuda_bf16.h>
#include <math.h>
#include <stdint.h>

// ---------------------------------------------------------------------------
// B=1, D=6, H=128, W=128, C=180, NH=6, HD=30, WS=(2,8,8) -> N=128/window,
// 768 windows, SS=(1,4,4), HID=360
// ---------------------------------------------------------------------------
#define NTOK   98304
#define CD     180
#define C3     540
#define C2     360
#define NWIN   768
#define NHEAD  6
#define HDIM   30
#define NMASK  16384
#define KP1    192
#define KP2    384
#define SCALE_F 0.18257418583505536f

// ------------------------- scratch (static, no alloc) ----------------------
__device__ __nv_bfloat16 g_a1 [(size_t)NTOK * KP1];
__device__ __nv_bfloat16 g_a1m[(size_t)NTOK * KP1];
__device__ __nv_bfloat16 g_qkv_s[(size_t)NTOK * C3];
__device__ __nv_bfloat16 g_qkv_m[(size_t)NTOK * C3];
__device__ __nv_bfloat16 g_xo  [(size_t)NTOK * KP2];
__device__ float         g_x1  [(size_t)NTOK * CD];
__device__ __nv_bfloat16 g_a2  [(size_t)NTOK * KP1];
__device__ __nv_bfloat16 g_hid [(size_t)NTOK * KP2];
__device__ float         g_bias6[NHEAD * NMASK];
__device__ __nv_bfloat16 g_wqs [640 * KP1];
__device__ __nv_bfloat16 g_wqm [640 * KP1];
__device__ __nv_bfloat16 g_wpr [256 * KP2];
__device__ __nv_bfloat16 g_wmix[768 * KP1];
__device__ __nv_bfloat16 g_wf2 [256 * KP2];

__device__ __forceinline__ int win2glob(int r) {
    int w = r >> 7, n = r & 127;
    int dblk = w >> 8, hblk = (w >> 4) & 15, wblk = w & 15;
    int wd = n >> 6,  wh = (n >> 3) & 7,   ww = n & 7;
    int d = dblk * 2 + wd + 1; if (d >= 6) d -= 6;
    int hh = (hblk * 8 + wh + 4) & 127;
    int w2 = (wblk * 8 + ww + 4) & 127;
    return (d * 128 + hh) * 128 + w2;
}

__device__ __forceinline__ uint32_t smem_u32(const void* p) {
    uint32_t a;
    asm("{ .reg .u64 t; cvta.to.shared.u64 t, %1; cvt.u32.u64 %0, t; }"
        : "=r"(a) : "l"(p));
    return a;
}

#define LDMATRIX_X4(r0, r1, r2, r3, addr) \
    asm volatile("ldmatrix.sync.aligned.m8n8.x4.shared.b16 {%0,%1,%2,%3}, [%4];" \
        : "=r"(r0), "=r"(r1), "=r"(r2), "=r"(r3) : "r"(addr))

#define MMA16816(d, a, b) \
    asm volatile("mma.sync.aligned.m16n8k16.row.col.f32.bf16.bf16.f32 " \
        "{%0,%1,%2,%3}, {%4,%5,%6,%7}, {%8,%9}, {%0,%1,%2,%3};" \
        : "+f"((d)[0]), "+f"((d)[1]), "+f"((d)[2]), "+f"((d)[3]) \
        : "r"((a)[0]), "r"((a)[1]), "r"((a)[2]), "r"((a)[3]), \
          "r"((b)[0]), "r"((b)[1]))

#define CP_ASYNC16(dst, src) \
    asm volatile("cp.async.cg.shared.global [%0], [%1], 16;" :: "r"(dst), "l"(src))
#define CP_COMMIT() asm volatile("cp.async.commit_group;")
#define CP_WAIT0()  asm volatile("cp.async.wait_group 0;")
#define CP_WAIT1()  asm volatile("cp.async.wait_group 1;")
#define CP_WAIT2()  asm volatile("cp.async.wait_group 2;")

// ------------------------- merged prep kernel ------------------------------
// segments: bias6 | wqsT | wqmT | wprT | wf2T | wmix | pad(xo+hid, uint4)
__global__ void prep_all(const float* __restrict__ rpb, const int* __restrict__ rpi,
                         const float* __restrict__ wqs, const float* __restrict__ wqm,
                         const float* __restrict__ wpr, const float* __restrict__ wf2,
                         const float* __restrict__ w11, const float* __restrict__ w12) {
    int idx = blockIdx.x * 256 + threadIdx.x;
    if (idx < 98304) {                                   // bias6 gather
        int h = idx >> 14, nm = idx & (NMASK - 1);
        g_bias6[idx] = rpb[rpi[nm] * NHEAD + h];
        return;
    }
    idx -= 98304;
    if (idx < 122880) {                                  // wqs^T (640 x 192)
        int n = idx / KP1, k = idx - n * KP1;
        g_wqs[idx] = __float2bfloat16((n < C3 && k < CD) ? wqs[(size_t)k * C3 + n] : 0.f);
        return;
    }
    idx -= 122880;
    if (idx < 122880) {                                  // wqm^T
        int n = idx / KP1, k = idx - n * KP1;
        g_wqm[idx] = __float2bfloat16((n < C3 && k < CD) ? wqm[(size_t)k * C3 + n] : 0.f);
        return;
    }
    idx -= 122880;
    if (idx < 98304) {                                   // wpr^T (256 x 384)
        int n = idx / KP2, k = idx - n * KP2;
        g_wpr[idx] = __float2bfloat16((n < CD && k < C2) ? wpr[(size_t)k * CD + n] : 0.f);
        return;
    }
    idx -= 98304;
    if (idx < 98304) {                                   // wf2^T (256 x 384)
        int n = idx / KP2, k = idx - n * KP2;
        g_wf2[idx] = __float2bfloat16((n < CD && k < C2) ? wf2[(size_t)k * CD + n] : 0.f);
        return;
    }
    idx -= 98304;
    if (idx < 147456) {                                  // wmix (768 x 192)
        int r = idx / KP1, k = idx - r * KP1;
        int n = r >> 1;
        float v = 0.f;
        if (k < CD && n < C2)
            v = (r & 1) ? w12[(size_t)k * C2 + n] : w11[(size_t)k * C2 + n];
        g_wmix[idx] = __float2bfloat16(v);
        return;
    }
    idx -= 147456;
    if (idx < 294912) {                                  // pad cols 360..383 (uint4)
        int r = idx / 3, s = idx - r * 3;
        uint4 z = make_uint4(0, 0, 0, 0);
        *(uint4*)(g_xo  + (size_t)r * KP2 + 360 + 8 * s) = z;
        *(uint4*)(g_hid + (size_t)r * KP2 + 360 + 8 * s) = z;
    }
}
#define PREP_TOTAL (98304 + 122880 + 122880 + 98304 + 98304 + 147456 + 294912)

// ------------------------- LayerNorms (warp/token, bf16 out) ---------------
__global__ void ln1_kernel(const float* __restrict__ x, const float* __restrict__ g,
                           const float* __restrict__ b, const float* __restrict__ pb) {
    int r = blockIdx.x * 8 + (threadIdx.x >> 5);
    int lane = threadIdx.x & 31;
    const float* xr = x + (size_t)win2glob(r) * CD;
    float vals[6], s = 0.f, s2 = 0.f;
#pragma unroll
    for (int i = 0; i < 6; i++) {
        int c = lane + i * 32;
        float v = (c < CD) ? xr[c] : 0.f;
        vals[i] = v; s += v; s2 += v * v;
    }
#pragma unroll
    for (int o = 16; o; o >>= 1) {
        s  += __shfl_xor_sync(0xffffffffu, s,  o);
        s2 += __shfl_xor_sync(0xffffffffu, s2, o);
    }
    float m = s * (1.f / CD);
    float rstd = rsqrtf(s2 * (1.f / CD) - m * m + 1e-5f);
    __nv_bfloat16* y1 = g_a1  + (size_t)r * KP1;
    __nv_bfloat16* y2 = g_a1m + (size_t)r * KP1;
    const float* pbr = pb + (size_t)(r & 63) * CD;
#pragma unroll
    for (int i = 0; i < 6; i++) {
        int c = lane + i * 32;
        if (c < CD) {
            float v = (vals[i] - m) * rstd * g[c] + b[c];
            y1[c] = __float2bfloat16(v);
            y2[c] = __float2bfloat16(v + pbr[c]);
        } else {
            y1[c] = __float2bfloat16(0.f);
            y2[c] = __float2bfloat16(0.f);
        }
    }
}

__global__ void ln2_kernel(const float* __restrict__ g, const float* __restrict__ b) {
    int r = blockIdx.x * 8 + (threadIdx.x >> 5);
    int lane = threadIdx.x & 31;
    const float* xr = g_x1 + (size_t)r * CD;
    float vals[6], s = 0.f, s2 = 0.f;
#pragma unroll
    for (int i = 0; i < 6; i++) {
        int c = lane + i * 32;
        float v = (c < CD) ? xr[c] : 0.f;
        vals[i] = v; s += v; s2 += v * v;
    }
#pragma unroll
    for (int o = 16; o; o >>= 1) {
        s  += __shfl_xor_sync(0xffffffffu, s,  o);
        s2 += __shfl_xor_sync(0xffffffffu, s2, o);
    }
    float m = s * (1.f / CD);
    float rstd = rsqrtf(s2 * (1.f / CD) - m * m + 1e-5f);
    __nv_bfloat16* y = g_a2 + (size_t)r * KP1;
#pragma unroll
    for (int i = 0; i < 6; i++) {
        int c = lane + i * 32;
        float v = (c < CD) ? (vals[i] - m) * rstd * g[c] + b[c] : 0.f;
        y[c] = __float2bfloat16(v);
    }
}

// ------------------------- GEMM body (device fn, 3-stage cp.async ring) ----
#define SBUF 9216   // halves per buffer (128*72)
template<int EPI>
__device__ __forceinline__ void gemm_body(
    const __nv_bfloat16* __restrict__ A, const __nv_bfloat16* __restrict__ Bt,
    const float* __restrict__ bias, const float* __restrict__ bias2,
    float* __restrict__ outF, __nv_bfloat16* __restrict__ outH,
    const float* __restrict__ resid,
    int ldA, int K, int Nreal, int bx, int by, __nv_bfloat16* smp)
{
    const int tid = threadIdx.x, lane = tid & 31, wid = tid >> 5;
    const int wm = wid >> 2, wn = wid & 3;
    const int row0 = by * 128, col0 = bx * 128;

    float acc[4][4][4];
#pragma unroll
    for (int a = 0; a < 4; a++)
#pragma unroll
        for (int b = 0; b < 4; b++)
#pragma unroll
            for (int c = 0; c < 4; c++) acc[a][b][c] = 0.f;

    auto stage = [&](int buf, int k0) {
        __nv_bfloat16* dA = smp + buf * SBUF;
        __nv_bfloat16* dB = smp + 3 * SBUF + buf * SBUF;
#pragma unroll
        for (int i = 0; i < 4; i++) {
            int u = tid + i * 256;
            int r = u >> 3, s = u & 7;
            CP_ASYNC16(smem_u32(dA + r * 72 + s * 8),
                       A + (size_t)(row0 + r) * ldA + k0 + s * 8);
            CP_ASYNC16(smem_u32(dB + r * 72 + s * 8),
                       Bt + (size_t)(col0 + r) * ldA + k0 + s * 8);
        }
    };

    const int nC = K / 64;
    const int nst = (nC < 3) ? nC : 3;
    for (int i = 0; i < nst; i++) { stage(i, i * 64); CP_COMMIT(); }

    for (int c = 0; c < nC; c++) {
        int wg = nC - 1 - c; if (wg > 2) wg = 2;
        if (wg == 2) CP_WAIT2(); else if (wg == 1) CP_WAIT1(); else CP_WAIT0();
        __syncthreads();

        int buf = c % 3;
        __nv_bfloat16 (*sA)[72] = (__nv_bfloat16(*)[72])(smp + buf * SBUF);
        __nv_bfloat16 (*sB)[72] = (__nv_bfloat16(*)[72])(smp + 3 * SBUF + buf * SBUF);

#pragma unroll
        for (int ks = 0; ks < 4; ks++) {
            int kk = ks * 16;
            uint32_t af[4][4];
#pragma unroll
            for (int mt = 0; mt < 4; mt++) {
                int mr = wm * 64 + mt * 16 + (lane & 15);
                int mc = kk + ((lane >> 4) << 3);
                LDMATRIX_X4(af[mt][0], af[mt][1], af[mt][2], af[mt][3],
                            smem_u32(&sA[mr][mc]));
            }
            uint32_t bfr[4][2];
#pragma unroll
            for (int np = 0; np < 2; np++) {
                int nr = wn * 32 + np * 16 + (lane & 7) + ((lane >> 4) << 3);
                int nc = kk + (((lane >> 3) & 1) << 3);
                uint32_t r0, r1, r2, r3;
                LDMATRIX_X4(r0, r1, r2, r3, smem_u32(&sB[nr][nc]));
                bfr[np * 2][0] = r0;     bfr[np * 2][1] = r1;
                bfr[np * 2 + 1][0] = r2; bfr[np * 2 + 1][1] = r3;
            }
#pragma unroll
            for (int mt = 0; mt < 4; mt++)
#pragma unroll
                for (int nt = 0; nt < 4; nt++)
                    MMA16816(acc[mt][nt], af[mt], bfr[nt]);
        }
        __syncthreads();
        if (c + 3 < nC) { stage((c + 3) % 3, (c + 3) * 64); CP_COMMIT(); }
    }

    const int mbase = row0 + wm * 64, nbase = col0 + wn * 32;
#pragma unroll
    for (int mt = 0; mt < 4; mt++) {
#pragma unroll
        for (int half = 0; half < 2; half++) {
            int rr = mbase + mt * 16 + (lane >> 2) + half * 8;
            if (EPI == 0) {
                __nv_bfloat16* o = outH + (size_t)rr * C3;
#pragma unroll
                for (int nt = 0; nt < 4; nt++) {
                    int c = nbase + nt * 8 + ((lane & 3) << 1);
                    if (c < Nreal) {
                        __nv_bfloat162 h;
                        h.x = __float2bfloat16(acc[mt][nt][half * 2]     + bias[c]);
                        h.y = __float2bfloat16(acc[mt][nt][half * 2 + 1] + bias[c + 1]);
                        *(__nv_bfloat162*)(o + c) = h;
                    }
                }
            } else if (EPI == 1 || EPI == 3) {
                int gI = (EPI == 1) ? win2glob(rr) : rr;
                float* o = outF + (size_t)gI * CD;
                const float* rs = resid + (size_t)gI * CD;
#pragma unroll
                for (int nt = 0; nt < 4; nt++) {
                    int c = nbase + nt * 8 + ((lane & 3) << 1);
                    if (c < Nreal) {
                        float2 rv = *(const float2*)(rs + c);
                        float2 ov;
                        ov.x = rv.x + acc[mt][nt][half * 2]     + bias[c];
                        ov.y = rv.y + acc[mt][nt][half * 2 + 1] + bias[c + 1];
                        *(float2*)(o + c) = ov;
                    }
                }
            } else { // EPI == 2
                __nv_bfloat16* o = outH + (size_t)rr * KP2;
#pragma unroll
                for (int nt = 0; nt < 4; nt++) {
                    int c = nbase + nt * 8 + ((lane & 3) << 1);
                    if (c < 720) {
                        int n = c >> 1;
                        float u = acc[mt][nt][half * 2]     + bias[n];
                        float v = acc[mt][nt][half * 2 + 1] + bias2[n];
                        float ge = 0.5f * u * (1.f + erff(u * 0.7071067811865475f));
                        o[n] = __float2bfloat16(ge * v);
                    }
                }
            }
        }
    }
}

template<int EPI>
__global__ __launch_bounds__(256) void mma_gemm(
    const __nv_bfloat16* __restrict__ A, const __nv_bfloat16* __restrict__ Bt,
    const float* __restrict__ bias, const float* __restrict__ bias2,
    float* __restrict__ outF, __nv_bfloat16* __restrict__ outH,
    const float* __restrict__ resid, int ldA, int K, int Nreal)
{
    extern __shared__ __align__(16) __nv_bfloat16 smp[];
    gemm_body<EPI>(A, Bt, bias, bias2, outF, outH, resid, ldA, K, Nreal,
                   blockIdx.x, blockIdx.y, smp);
}

// qkv self+mut merged: grid.z selects parameter set
__global__ __launch_bounds__(256) void mma_gemm_qkv(
    const __nv_bfloat16* __restrict__ A0, const __nv_bfloat16* __restrict__ A1,
    const __nv_bfloat16* __restrict__ B0, const __nv_bfloat16* __restrict__ B1,
    const float* __restrict__ bias0, const float* __restrict__ bias1,
    __nv_bfloat16* __restrict__ out0, __nv_bfloat16* __restrict__ out1)
{
    extern __shared__ __align__(16) __nv_bfloat16 smp[];
    if (blockIdx.z == 0)
        gemm_body<0>(A0, B0, bias0, nullptr, nullptr, out0, nullptr,
                     KP1, KP1, C3, blockIdx.x, blockIdx.y, smp);
    else
        gemm_body<0>(A1, B1, bias1, nullptr, nullptr, out1, nullptr,
                     KP1, KP1, C3, blockIdx.x, blockIdx.y, smp);
}

// ------------------------- fused attention (self + mutual) -----------------
// blocks [0, 4608): self (window, head);  [4608, 9216): mutual pair (both parts)
#define ASM_QB   0
#define ASM_KB   10240
#define ASM_VT   20480
#define ASM_BM   29184
#define ASM_TOT  62976

__device__ __forceinline__ void attn_self_body(char* smc, const float* __restrict__ mask,
                                               int blk) {
    __nv_bfloat16 (*Qb)[40]  = (__nv_bfloat16(*)[40])(smc + ASM_QB);
    __nv_bfloat16 (*Kb)[40]  = (__nv_bfloat16(*)[40])(smc + ASM_KB);
    __nv_bfloat16 (*Vt)[136] = (__nv_bfloat16(*)[136])(smc + ASM_VT);
    __nv_bfloat16* bm        = (__nv_bfloat16*)(smc + ASM_BM);  // stride 132

    int w = blk / NHEAD, h = blk % NHEAD;
    int tid = threadIdx.x, lane = tid & 31, wid = tid >> 5;
    const __nv_bfloat16* base = g_qkv_s + (size_t)w * 128 * C3;

    for (int idx = tid; idx < 128 * 32; idx += 128) {
        int m = idx >> 5, d = idx & 31;
        __nv_bfloat16 z = __float2bfloat16(0.f);
        Qb[m][d] = (d < HDIM) ? base[(size_t)m * C3 + h * HDIM + d]          : z;
        Kb[m][d] = (d < HDIM) ? base[(size_t)m * C3 + CD + h * HDIM + d]     : z;
        Vt[d][m] = (d < HDIM) ? base[(size_t)m * C3 + 2 * CD + h * HDIM + d] : z;
    }
    {
        const float* bi = g_bias6 + h * NMASK;
        const float* mk = mask + (size_t)w * NMASK;
        for (int idx = tid; idx < NMASK; idx += 128) {
            int n = idx >> 7, m = idx & 127;
            bm[n * 132 + m] = __float2bfloat16(bi[idx] + mk[idx]);
        }
    }
    __syncthreads();

    float accS[2][16][4];
#pragma unroll
    for (int a = 0; a < 2; a++)
#pragma unroll
        for (int t = 0; t < 16; t++)
#pragma unroll
            for (int c = 0; c < 4; c++) accS[a][t][c] = 0.f;

#pragma unroll
    for (int ks = 0; ks < 2; ks++) {
        int kk = ks * 16;
        uint32_t af[2][4];
#pragma unroll
        for (int mt = 0; mt < 2; mt++) {
            int mr = wid * 32 + mt * 16 + (lane & 15);
            int mc = kk + ((lane >> 4) << 3);
            LDMATRIX_X4(af[mt][0], af[mt][1], af[mt][2], af[mt][3],
                        smem_u32(&Qb[mr][mc]));
        }
#pragma unroll
        for (int j = 0; j < 8; j++) {
            int nr = j * 16 + (lane & 7) + ((lane >> 4) << 3);
            int nc = kk + (((lane >> 3) & 1) << 3);
            uint32_t r0, r1, r2, r3;
            LDMATRIX_X4(r0, r1, r2, r3, smem_u32(&Kb[nr][nc]));
            uint32_t b0[2] = {r0, r1}, b1[2] = {r2, r3};
#pragma unroll
            for (int mt = 0; mt < 2; mt++) {
                MMA16816(accS[mt][2 * j],     af[mt], b0);
                MMA16816(accS[mt][2 * j + 1], af[mt], b1);
            }
        }
    }

    uint32_t pf[2][16][2];
    float linv[2][2];
#pragma unroll
    for (int mt = 0; mt < 2; mt++) {
        int row0 = wid * 32 + mt * 16 + (lane >> 2);
        int row1 = row0 + 8;
        float mx0 = -1e30f, mx1 = -1e30f;
#pragma unroll
        for (int t = 0; t < 16; t++) {
            int col = t * 8 + ((lane & 3) << 1);
            uint32_t u0 = *(const uint32_t*)(bm + row0 * 132 + col);
            uint32_t u1 = *(const uint32_t*)(bm + row1 * 132 + col);
            __nv_bfloat162 h0 = *(__nv_bfloat162*)&u0;
            __nv_bfloat162 h1 = *(__nv_bfloat162*)&u1;
            accS[mt][t][0] = accS[mt][t][0] * SCALE_F + __bfloat162float(h0.x);
            accS[mt][t][1] = accS[mt][t][1] * SCALE_F + __bfloat162float(h0.y);
            accS[mt][t][2] = accS[mt][t][2] * SCALE_F + __bfloat162float(h1.x);
            accS[mt][t][3] = accS[mt][t][3] * SCALE_F + __bfloat162float(h1.y);
            mx0 = fmaxf(mx0, fmaxf(accS[mt][t][0], accS[mt][t][1]));
            mx1 = fmaxf(mx1, fmaxf(accS[mt][t][2], accS[mt][t][3]));
        }
        mx0 = fmaxf(mx0, __shfl_xor_sync(0xffffffffu, mx0, 1));
        mx0 = fmaxf(mx0, __shfl_xor_sync(0xffffffffu, mx0, 2));
        mx1 = fmaxf(mx1, __shfl_xor_sync(0xffffffffu, mx1, 1));
        mx1 = fmaxf(mx1, __shfl_xor_sync(0xffffffffu, mx1, 2));
        float l0 = 0.f, l1 = 0.f;
#pragma unroll
        for (int t = 0; t < 16; t++) {
            float p0 = __expf(accS[mt][t][0] - mx0);
            float p1 = __expf(accS[mt][t][1] - mx0);
            float p2 = __expf(accS[mt][t][2] - mx1);
            float p3 = __expf(accS[mt][t][3] - mx1);
            l0 += p0 + p1; l1 += p2 + p3;
            __nv_bfloat162 q0 = __floats2bfloat162_rn(p0, p1);
            __nv_bfloat162 q1 = __floats2bfloat162_rn(p2, p3);
            pf[mt][t][0] = *(uint32_t*)&q0;
            pf[mt][t][1] = *(uint32_t*)&q1;
        }
        l0 += __shfl_xor_sync(0xffffffffu, l0, 1);
        l0 += __shfl_xor_sync(0xffffffffu, l0, 2);
        l1 += __shfl_xor_sync(0xffffffffu, l1, 1);
        l1 += __shfl_xor_sync(0xffffffffu, l1, 2);
        linv[mt][0] = 1.f / l0;
        linv[mt][1] = 1.f / l1;
    }

    float accO[2][4][4];
#pragma unroll
    for (int a = 0; a < 2; a++)
#pragma unroll
        for (int b = 0; b < 4; b++)
#pragma unroll
            for (int c = 0; c < 4; c++) accO[a][b][c] = 0.f;

#pragma unroll
    for (int ks = 0; ks < 8; ks++) {
        uint32_t bfr[4][2];
#pragma unroll
        for (int np = 0; np < 2; np++) {
            int nr = np * 16 + (lane & 7) + ((lane >> 4) << 3);
            int nc = ks * 16 + (((lane >> 3) & 1) << 3);
            uint32_t r0, r1, r2, r3;
            LDMATRIX_X4(r0, r1, r2, r3, smem_u32(&Vt[nr][nc]));
            bfr[np * 2][0] = r0;     bfr[np * 2][1] = r1;
            bfr[np * 2 + 1][0] = r2; bfr[np * 2 + 1][1] = r3;
        }
#pragma unroll
        for (int mt = 0; mt < 2; mt++) {
            uint32_t am[4] = {pf[mt][2 * ks][0], pf[mt][2 * ks][1],
                              pf[mt][2 * ks + 1][0], pf[mt][2 * ks + 1][1]};
#pragma unroll
            for (int nt = 0; nt < 4; nt++)
                MMA16816(accO[mt][nt], am, bfr[nt]);
        }
    }

#pragma unroll
    for (int mt = 0; mt < 2; mt++) {
#pragma unroll
        for (int half = 0; half < 2; half++) {
            int row = wid * 32 + mt * 16 + (lane >> 2) + half * 8;
            float inv = linv[mt][half];
            __nv_bfloat16* o = g_xo + (size_t)(w * 128 + row) * KP2 + CD + h * HDIM;
#pragma unroll
            for (int nt = 0; nt < 4; nt++) {
                int col = nt * 8 + ((lane & 3) << 1);
                if (col < HDIM) {
                    __nv_bfloat162 hv;
                    hv.x = __float2bfloat16(accO[mt][nt][half * 2]     * inv);
                    hv.y = __float2bfloat16(accO[mt][nt][half * 2 + 1] * inv);
                    *(__nv_bfloat162*)(o + col) = hv;
                }
            }
        }
    }
}

// mutual pair: 128 threads, tid>>6 = part (0/1); one shared 64x64 mask tile
#define AMU_QB  0        // [2][64][40] bf16 = 10240
#define AMU_KB  10240    // [2][64][40]      = 10240
#define AMU_VT  20480    // [2][32][72]      = 9216
#define AMU_BM  29696    // [64*68]          = 8704  (shared by both parts)
__device__ __forceinline__ void attn_mut_body(char* smc, const float* __restrict__ mask,
                                              int blk) {
    __nv_bfloat16 (*Qb)[64][40] = (__nv_bfloat16(*)[64][40])(smc + AMU_QB);
    __nv_bfloat16 (*Kb)[64][40] = (__nv_bfloat16(*)[64][40])(smc + AMU_KB);
    __nv_bfloat16 (*Vt)[32][72] = (__nv_bfloat16(*)[32][72])(smc + AMU_VT);
    __nv_bfloat16* bm           = (__nv_bfloat16*)(smc + AMU_BM);  // stride 68

    int h = blk % NHEAD, w = blk / NHEAD;
    int tid = threadIdx.x, lane = tid & 31;
    int part = tid >> 6, ptid = tid & 63, wid2 = ptid >> 5;
    const __nv_bfloat16* base = g_qkv_m + (size_t)w * 128 * C3;
    int kvoff = part * 64;
    int qoff  = 64 - kvoff;

    for (int idx = ptid; idx < 64 * 32; idx += 64) {
        int m = idx >> 5, d = idx & 31;
        __nv_bfloat16 z = __float2bfloat16(0.f);
        Qb[part][m][d] = (d < HDIM) ? base[(size_t)(qoff + m) * C3 + h * HDIM + d]           : z;
        Kb[part][m][d] = (d < HDIM) ? base[(size_t)(kvoff + m) * C3 + CD + h * HDIM + d]     : z;
        Vt[part][d][m] = (d < HDIM) ? base[(size_t)(kvoff + m) * C3 + 2 * CD + h * HDIM + d] : z;
    }
    {
        const float* mk = mask + (size_t)w * NMASK;   // top-left 64x64 block
        for (int idx = tid; idx < 64 * 64; idx += 128) {
            int n = idx >> 6, m = idx & 63;
            bm[n * 68 + m] = __float2bfloat16(mk[n * 128 + m]);
        }
    }
    __syncthreads();

    float accS[2][8][4];
#pragma unroll
    for (int a = 0; a < 2; a++)
#pragma unroll
        for (int t = 0; t < 8; t++)
#pragma unroll
            for (int c = 0; c < 4; c++) accS[a][t][c] = 0.f;

#pragma unroll
    for (int ks = 0; ks < 2; ks++) {
        int kk = ks * 16;
        uint32_t af[2][4];
#pragma unroll
        for (int mt = 0; mt < 2; mt++) {
            int mr = wid2 * 32 + mt * 16 + (lane & 15);
            int mc = kk + ((lane >> 4) << 3);
            LDMATRIX_X4(af[mt][0], af[mt][1], af[mt][2], af[mt][3],
                        smem_u32(&Qb[part][mr][mc]));
        }
#pragma unroll
        for (int j = 0; j < 4; j++) {
            int nr = j * 16 + (lane & 7) + ((lane >> 4) << 3);
            int nc = kk + (((lane >> 3) & 1) << 3);
            uint32_t r0, r1, r2, r3;
            LDMATRIX_X4(r0, r1, r2, r3, smem_u32(&Kb[part][nr][nc]));
            uint32_t b0[2] = {r0, r1}, b1[2] = {r2, r3};
#pragma unroll
            for (int mt = 0; mt < 2; mt++) {
                MMA16816(accS[mt][2 * j],     af[mt], b0);
                MMA16816(accS[mt][2 * j + 1], af[mt], b1);
            }
        }
    }

    uint32_t pf[2][8][2];
    float linv[2][2];
#pragma unroll
    for (int mt = 0; mt < 2; mt++) {
        int row0 = wid2 * 32 + mt * 16 + (lane >> 2);
        int row1 = row0 + 8;
        float mx0 = -1e30f, mx1 = -1e30f;
#pragma unroll
        for (int t = 0; t < 8; t++) {
            int col = t * 8 + ((lane & 3) << 1);
            uint32_t u0 = *(const uint32_t*)(bm + row0 * 68 + col);
            uint32_t u1 = *(const uint32_t*)(bm + row1 * 68 + col);
            __nv_bfloat162 h0 = *(__nv_bfloat162*)&u0;
            __nv_bfloat162 h1 = *(__nv_bfloat162*)&u1;
            accS[mt][t][0] = accS[mt][t][0] * SCALE_F + __bfloat162float(h0.x);
            accS[mt][t][1] = accS[mt][t][1] * SCALE_F + __bfloat162float(h0.y);
            accS[mt][t][2] = accS[mt][t][2] * SCALE_F + __bfloat162float(h1.x);
            accS[mt][t][3] = accS[mt][t][3] * SCALE_F + __bfloat162float(h1.y);
            mx0 = fmaxf(mx0, fmaxf(accS[mt][t][0], accS[mt][t][1]));
            mx1 = fmaxf(mx1, fmaxf(accS[mt][t][2], accS[mt][t][3]));
        }
        mx0 = fmaxf(mx0, __shfl_xor_sync(0xffffffffu, mx0, 1));
        mx0 = fmaxf(mx0, __shfl_xor_sync(0xffffffffu, mx0, 2));
        mx1 = fmaxf(mx1, __shfl_xor_sync(0xffffffffu, mx1, 1));
        mx1 = fmaxf(mx1, __shfl_xor_sync(0xffffffffu, mx1, 2));
        float l0 = 0.f, l1 = 0.f;
#pragma unroll
        for (int t = 0; t < 8; t++) {
            float p0 = __expf(accS[mt][t][0] - mx0);
            float p1 = __expf(accS[mt][t][1] - mx0);
            float p2 = __expf(accS[mt][t][2] - mx1);
            float p3 = __expf(accS[mt][t][3] - mx1);
            l0 += p0 + p1; l1 += p2 + p3;
            __nv_bfloat162 q0 = __floats2bfloat162_rn(p0, p1);
            __nv_bfloat162 q1 = __floats2bfloat162_rn(p2, p3);
            pf[mt][t][0] = *(uint32_t*)&q0;
            pf[mt][t][1] = *(uint32_t*)&q1;
        }
        l0 += __shfl_xor_sync(0xffffffffu, l0, 1);
        l0 += __shfl_xor_sync(0xffffffffu, l0, 2);
        l1 += __shfl_xor_sync(0xffffffffu, l1, 1);
        l1 += __shfl_xor_sync(0xffffffffu, l1, 2);
        linv[mt][0] = 1.f / l0;
        linv[mt][1] = 1.f / l1;
    }

    float accO[2][4][4];
#pragma unroll
    for (int a = 0; a < 2; a++)
#pragma unroll
        for (int b2_ = 0; b2_ < 4; b2_++)
#pragma unroll
            for (int c = 0; c < 4; c++) accO[a][b2_][c] = 0.f;

#pragma unroll
    for (int ks = 0; ks < 4; ks++) {
        uint32_t bfr[4][2];
#pragma unroll
        for (int np = 0; np < 2; np++) {
            int nr = np * 16 + (lane & 7) + ((lane >> 4) << 3);
            int nc = ks * 16 + (((lane >> 3) & 1) << 3);
            uint32_t r0, r1, r2, r3;
            LDMATRIX_X4(r0, r1, r2, r3, smem_u32(&Vt[part][nr][nc]));
            bfr[np * 2][0] = r0;     bfr[np * 2][1] = r1;
            bfr[np * 2 + 1][0] = r2; bfr[np * 2 + 1][1] = r3;
        }
#pragma unroll
        for (int mt = 0; mt < 2; mt++) {
            uint32_t am[4] = {pf[mt][2 * ks][0], pf[mt][2 * ks][1],
                              pf[mt][2 * ks + 1][0], pf[mt][2 * ks + 1][1]};
#pragma unroll
            for (int nt = 0; nt < 4; nt++)
                MMA16816(accO[mt][nt], am, bfr[nt]);
        }
    }

#pragma unroll
    for (int mt = 0; mt < 2; mt++) {
#pragma unroll
        for (int half = 0; half < 2; half++) {
            int row = wid2 * 32 + mt * 16 + (lane >> 2) + half * 8;
            float inv = linv[mt][half];
            __nv_bfloat16* o = g_xo + (size_t)(w * 128 + part * 64 + row) * KP2 + h * HDIM;
#pragma unroll
            for (int nt = 0; nt < 4; nt++) {
                int col = nt * 8 + ((lane & 3) << 1);
                if (col < HDIM) {
                    __nv_bfloat162 hv;
                    hv.x = __float2bfloat16(accO[mt][nt][half * 2]     * inv);
                    hv.y = __float2bfloat16(accO[mt][nt][half * 2 + 1] * inv);
                    *(__nv_bfloat162*)(o + col) = hv;
                }
            }
        }
    }
}

__global__ __launch_bounds__(128) void attn_fused(const float* __restrict__ mask) {
    extern __shared__ __align__(16) char smc[];
    int blk = blockIdx.x;
    if (blk < NWIN * NHEAD) attn_self_body(smc, mask, blk);
    else                    attn_mut_body(smc, mask, blk - NWIN * NHEAD);
}

// ---------------------------------------------------------------------------
extern "C" void kernel_launch(void* const* d_in, const int* in_sizes, int n_in,
                              void* d_out, int out_size) {
    const float* x          = (const float*)d_in[0];
    const float* mask       = (const float*)d_in[1];
    const float* g1         = (const float*)d_in[2];
    const float* b1         = (const float*)d_in[3];
    const float* g2         = (const float*)d_in[4];
    const float* b2         = (const float*)d_in[5];
    const float* w_qkv_self = (const float*)d_in[6];
    const float* b_qkv_self = (const float*)d_in[7];
    const float* w_qkv_mut  = (const float*)d_in[8];
    const float* b_qkv_mut  = (const float*)d_in[9];
    const float* rpb_table  = (const float*)d_in[10];
    const float* pos_bias   = (const float*)d_in[11];
    const float* w_proj     = (const float*)d_in[12];
    const float* b_proj     = (const float*)d_in[13];
    const float* w_fc11     = (const float*)d_in[14];
    const float* b_fc11     = (const float*)d_in[15];
    const float* w_fc12     = (const float*)d_in[16];
    const float* b_fc12     = (const float*)d_in[17];
    const float* w_fc2      = (const float*)d_in[18];
    const float* b_fc2      = (const float*)d_in[19];
    const int*   rpi        = (const int*)d_in[20];
    float* out = (float*)d_out;

    __nv_bfloat16 *p_a1, *p_a1m, *p_qs, *p_qm, *p_xo, *p_a2, *p_hid;
    __nv_bfloat16 *p_wqs, *p_wqm, *p_wpr, *p_wmix, *p_wf2;
    float *p_x1;
    cudaGetSymbolAddress((void**)&p_a1,  g_a1);
    cudaGetSymbolAddress((void**)&p_a1m, g_a1m);
    cudaGetSymbolAddress((void**)&p_qs,  g_qkv_s);
    cudaGetSymbolAddress((void**)&p_qm,  g_qkv_m);
    cudaGetSymbolAddress((void**)&p_xo,  g_xo);
    cudaGetSymbolAddress((void**)&p_a2,  g_a2);
    cudaGetSymbolAddress((void**)&p_hid, g_hid);
    cudaGetSymbolAddress((void**)&p_x1,  g_x1);
    cudaGetSymbolAddress((void**)&p_wqs, g_wqs);
    cudaGetSymbolAddress((void**)&p_wqm, g_wqm);
    cudaGetSymbolAddress((void**)&p_wpr, g_wpr);
    cudaGetSymbolAddress((void**)&p_wmix,g_wmix);
    cudaGetSymbolAddress((void**)&p_wf2, g_wf2);

    cudaFuncSetAttribute(attn_fused,
                         cudaFuncAttributeMaxDynamicSharedMemorySize, ASM_TOT);

    int gemm_smem = 6 * SBUF * 2;   // 110592 B (A[3] + B[3])
    cudaFuncSetAttribute(mma_gemm_qkv, cudaFuncAttributeMaxDynamicSharedMemorySize, gemm_smem);
    cudaFuncSetAttribute(mma_gemm<1>, cudaFuncAttributeMaxDynamicSharedMemorySize, gemm_smem);
    cudaFuncSetAttribute(mma_gemm<2>, cudaFuncAttributeMaxDynamicSharedMemorySize, gemm_smem);
    cudaFuncSetAttribute(mma_gemm<3>, cudaFuncAttributeMaxDynamicSharedMemorySize, gemm_smem);

    // 1) merged prep
    prep_all<<<(PREP_TOTAL + 255) / 256, 256>>>(rpb_table, rpi, w_qkv_self, w_qkv_mut,
                                                w_proj, w_fc2, w_fc11, w_fc12);
    // 2) LN1 + roll + window partition
    ln1_kernel<<<NTOK / 8, 256>>>(x, g1, b1, pos_bias);
    // 3) both qkv GEMMs in one launch
    mma_gemm_qkv<<<dim3(5, NTOK / 128, 2), 256, gemm_smem>>>(
        p_a1, p_a1m, p_wqs, p_wqm, b_qkv_self, b_qkv_mut, p_qs, p_qm);
    // 4) fused attention (self + mutual)
    attn_fused<<<2 * NWIN * NHEAD, 128, ASM_TOT>>>(mask);
    // 5) proj (+win_rev+roll+resid)
    mma_gemm<1><<<dim3(2, NTOK / 128), 256, gemm_smem>>>(p_xo, p_wpr, b_proj, nullptr,
                                              p_x1, nullptr, x, KP2, KP2, CD);
    // 6) LN2
    ln2_kernel<<<NTOK / 8, 256>>>(g2, b2);
    // 7) fc1 (fused GEGLU)
    mma_gemm<2><<<dim3(6, NTOK / 128), 256, gemm_smem>>>(p_a2, p_wmix, b_fc11, b_fc12,
                                              nullptr, p_hid, nullptr, KP1, KP1, 720);
    // 8) fc2 + residual
    mma_gemm<3><<<dim3(2, NTOK / 128), 256, gemm_smem>>>(p_hid, p_wf2, b_fc2, nullptr,
                                              out, nullptr, p_x1, KP2, KP2, CD);
    (void)in_sizes; (void)n_in; (void)out_size;
}